// round 1
// baseline (speedup 1.0000x reference)
#include <cuda_runtime.h>
#include <math.h>

#define BB   8
#define NS   25
#define NQ   75
#define WAY  5
#define CCH  512
#define HW   36
#define MID  6
#define NCLS 64
#define PAIRS (BB*WAY*NQ)   /* 3000 */
#define CHW  (CCH*HW)       /* 18432 */
#define M_A  (WAY*HW)       /* 180  */
#define N_A  (NQ*HW)        /* 2700 */

// ---------------- scratch (device globals; no allocation) ----------------
__device__ float g_protos[BB*WAY*CHW];        // [b,i,c,x]
__device__ float g_f1nT [BB*WAY*HW*CCH];      // [b,i,x,c]  (l2-normalized over c)
__device__ float g_f2nT [BB*NQ*HW*CCH];       // [b,q,x,c]  (l2-normalized over c)
__device__ float g_a1   [BB*M_A*N_A];         // [b, i*36+x, j*36+y]
__device__ float g_y    [2*PAIRS*MID];        // conv1 outputs, path1 then path2
__device__ float g_stats[4*MID];              // sum1, sq1, sum2, sq2
__device__ float g_bnp  [4*MID];              // mu1, istd1, mu2, istd2
__device__ float g_att1 [PAIRS*HW];           // [ (b*5+i)*75+j , x ]
__device__ float g_att2 [PAIRS*HW];           // [ (b*5+i)*75+j , y ]
__device__ float g_pnorm[BB*NQ*WAY*CCH];      // [b,q,i,c]  normalized pooled protos

// ---------------- kernels ----------------
__global__ void k_zero() {
    int t = threadIdx.x;
    if (t < 4*MID) g_stats[t] = 0.f;
}

// prototypes: protos[b,w,d] = sum_n st[b,n,w]*sup[b,n,d] / cnt[b,w]
__global__ void k_protos(const float* __restrict__ sup, const float* __restrict__ st) {
    int b = blockIdx.y;
    int t = threadIdx.x;
    __shared__ float sts[NS*WAY];
    __shared__ float cnt[WAY];
    if (t < NS*WAY) sts[t] = st[b*NS*WAY + t];
    __syncthreads();
    if (t < WAY) { float s = 0.f; for (int n = 0; n < NS; n++) s += sts[n*WAY + t]; cnt[t] = s; }
    __syncthreads();
    int d = blockIdx.x*256 + t;
    if (d >= CHW) return;
    float acc[WAY] = {0.f,0.f,0.f,0.f,0.f};
    const float* sb = sup + (size_t)b*NS*CHW + d;
    for (int n = 0; n < NS; n++) {
        float v = sb[(size_t)n*CHW];
        #pragma unroll
        for (int w = 0; w < WAY; w++) acc[w] += sts[n*WAY + w]*v;
    }
    #pragma unroll
    for (int w = 0; w < WAY; w++)
        g_protos[(size_t)(b*WAY + w)*CHW + d] = acc[w]/cnt[w];
}

// l2-normalize over c and transpose [c,x] -> [x,c]; one block per (row = b*n + n)
__device__ __forceinline__ void normT_core(const float* __restrict__ s, float* __restrict__ d) {
    __shared__ float tile[32][37];
    __shared__ float ssq[HW];
    __shared__ float rn[HW];
    int t = threadIdx.x;  // 256
    if (t < HW) ssq[t] = 0.f;
    __syncthreads();
    for (int c0 = 0; c0 < CCH; c0 += 32) {
        for (int idx = t; idx < 32*HW; idx += 256) {
            int cc = idx/HW, x = idx%HW;
            tile[cc][x] = s[(c0 + cc)*HW + x];
        }
        __syncthreads();
        if (t < HW) {
            float a = 0.f;
            #pragma unroll
            for (int cc = 0; cc < 32; cc++) { float v = tile[cc][t]; a += v*v; }
            ssq[t] += a;
        }
        __syncthreads();
    }
    if (t < HW) rn[t] = 1.f/fmaxf(sqrtf(ssq[t]), 1e-12f);
    __syncthreads();
    for (int c0 = 0; c0 < CCH; c0 += 32) {
        for (int idx = t; idx < 32*HW; idx += 256) {
            int cc = idx/HW, x = idx%HW;
            tile[cc][x] = s[(c0 + cc)*HW + x];
        }
        __syncthreads();
        for (int idx = t; idx < 32*HW; idx += 256) {
            int cc = idx & 31, x = idx >> 5;
            d[x*CCH + c0 + cc] = tile[cc][x]*rn[x];
        }
        __syncthreads();
    }
}

__global__ void k_norm1() {  // protos -> f1nT
    int row = blockIdx.x;
    normT_core(g_protos + (size_t)row*CHW, g_f1nT + (size_t)row*CHW);
}
__global__ void k_norm2(const float* __restrict__ query) {  // query -> f2nT
    int row = blockIdx.x;
    normT_core(query + (size_t)row*CHW, g_f2nT + (size_t)row*CHW);
}

// batched NT GEMM: a1[b] (180 x 2700) = f1nT[b] (180x512) * f2nT[b]^T (512x2700)
__global__ void __launch_bounds__(256) k_gemm() {
    int bb = blockIdx.z;
    const float* A  = g_f1nT + (size_t)bb*M_A*CCH;
    const float* Bm = g_f2nT + (size_t)bb*N_A*CCH;
    float*       Cm = g_a1   + (size_t)bb*M_A*N_A;
    int m0 = blockIdx.y*64, n0 = blockIdx.x*64;
    __shared__ float As[16][65];
    __shared__ float Bs[16][65];
    int t  = threadIdx.x;
    int tx = t & 15, ty = t >> 4;
    int lk = t & 15, lr = t >> 4;
    float acc[4][4];
    #pragma unroll
    for (int i = 0; i < 4; i++)
        #pragma unroll
        for (int j = 0; j < 4; j++) acc[i][j] = 0.f;
    for (int k0 = 0; k0 < CCH; k0 += 16) {
        #pragma unroll
        for (int r = 0; r < 4; r++) {
            int m = lr + r*16;
            int gm = m0 + m, gn = n0 + m;
            As[lk][m] = (gm < M_A) ? A [(size_t)gm*CCH + k0 + lk] : 0.f;
            Bs[lk][m] = (gn < N_A) ? Bm[(size_t)gn*CCH + k0 + lk] : 0.f;
        }
        __syncthreads();
        #pragma unroll
        for (int k = 0; k < 16; k++) {
            float av[4], bv[4];
            #pragma unroll
            for (int i = 0; i < 4; i++) { av[i] = As[k][ty + 16*i]; bv[i] = Bs[k][tx + 16*i]; }
            #pragma unroll
            for (int i = 0; i < 4; i++)
                #pragma unroll
                for (int j = 0; j < 4; j++) acc[i][j] += av[i]*bv[j];
        }
        __syncthreads();
    }
    #pragma unroll
    for (int i = 0; i < 4; i++) {
        int m = m0 + ty + 16*i;
        if (m >= M_A) continue;
        #pragma unroll
        for (int j = 0; j < 4; j++) {
            int n = n0 + tx + 16*j;
            if (n < N_A) Cm[(size_t)m*N_A + n] = acc[i][j];
        }
    }
}

// per-pair row/col means -> conv1 -> global BN stats
__global__ void k_attpre(const float* __restrict__ w1, const float* __restrict__ b1) {
    int p = blockIdx.x;
    int b = p/(WAY*NQ); int rem = p%(WAY*NQ); int i = rem/NQ; int j = rem%NQ;
    const float* A = g_a1 + (size_t)b*M_A*N_A + (size_t)(i*HW)*N_A + j*HW;
    __shared__ float sm1[HW];  // sum over x -> fn of y
    __shared__ float sm2[HW];  // sum over y -> fn of x
    int t = threadIdx.x;  // 128
    if (t < HW) { sm1[t] = 0.f; sm2[t] = 0.f; }
    __syncthreads();
    for (int idx = t; idx < HW*HW; idx += 128) {
        int x = idx/HW, y = idx%HW;
        float v = A[(size_t)x*N_A + y];
        atomicAdd(&sm1[y], v);
        atomicAdd(&sm2[x], v);
    }
    __syncthreads();
    if (t < 2*MID) {
        int o = t % MID;
        const float* m = (t < MID) ? sm1 : sm2;
        float a = 0.f;
        #pragma unroll
        for (int y = 0; y < HW; y++) a += w1[o*HW + y]*m[y];
        a = b1[o] + a*(1.f/36.f);
        int path = (t < MID) ? 0 : 1;
        g_y[path*PAIRS*MID + p*MID + o] = a;
        atomicAdd(&g_stats[path*2*MID + o],        a);
        atomicAdd(&g_stats[path*2*MID + MID + o],  a*a);
    }
}

__global__ void k_bnfin() {
    int t = threadIdx.x;
    if (t < 2*MID) {
        int path = t/MID, o = t%MID;
        float sum = g_stats[path*2*MID + o];
        float sq  = g_stats[path*2*MID + MID + o];
        float mu  = sum/(float)PAIRS;
        float var = sq/(float)PAIRS - mu*mu;
        g_bnp[path*2*MID + o]       = mu;
        g_bnp[path*2*MID + MID + o] = rsqrtf(var + 1e-5f);
    }
}

// BN+relu+conv2 -> attention weights -> matvec with A -> softmax(*40)+1, both paths
__global__ void k_att(const float* __restrict__ gam, const float* __restrict__ bet,
                      const float* __restrict__ w2,  const float* __restrict__ b2) {
    int p = blockIdx.x;
    int b = p/(WAY*NQ); int rem = p%(WAY*NQ); int i = rem/NQ; int j = rem%NQ;
    const float* A = g_a1 + (size_t)b*M_A*N_A + (size_t)(i*HW)*N_A + j*HW;
    __shared__ float h[2*MID];
    __shared__ float aw1[HW], aw2[HW];
    __shared__ float s1[HW],  s2[HW];
    __shared__ float red[4];
    int t = threadIdx.x;  // 128
    if (t < 2*MID) {
        int path = t/MID, o = t%MID;
        float v   = g_y[path*PAIRS*MID + p*MID + o];
        float mu  = g_bnp[path*2*MID + o];
        float ist = g_bnp[path*2*MID + MID + o];
        float z = gam[o]*(v - mu)*ist + bet[o];
        h[t] = fmaxf(z, 0.f);
    }
    __syncthreads();
    if (t < 2*HW) {
        int path = t/HW, y = t%HW;
        float a = b2[y];
        #pragma unroll
        for (int o = 0; o < MID; o++) a += w2[y*MID + o]*h[path*MID + o];
        if (path == 0) aw1[y] = a; else aw2[y] = a;
    }
    __syncthreads();
    if (t < HW) {                    // s1[x] = mean_y A[x,y]*aw1[y]
        float a = 0.f;
        #pragma unroll
        for (int y = 0; y < HW; y++) a += A[(size_t)t*N_A + y]*aw1[y];
        s1[t] = a*(1.f/36.f);
    } else if (t < 2*HW) {           // s2[y] = mean_x A[x,y]*aw2[x]
        int y = t - HW;
        float a = 0.f;
        #pragma unroll
        for (int x = 0; x < HW; x++) a += A[(size_t)x*N_A + y]*aw2[x];
        s2[y] = a*(1.f/36.f);
    }
    __syncthreads();
    if (t == 0)  { float m = -1e30f; for (int x = 0; x < HW; x++) m = fmaxf(m, s1[x]); red[0] = m; }
    if (t == 64) { float m = -1e30f; for (int y = 0; y < HW; y++) m = fmaxf(m, s2[y]); red[1] = m; }
    __syncthreads();
    if (t < HW)        s1[t]      = expf((s1[t]      - red[0])*40.f);
    else if (t < 2*HW) s2[t - HW] = expf((s2[t - HW] - red[1])*40.f);
    __syncthreads();
    if (t == 0)  { float s = 0.f; for (int x = 0; x < HW; x++) s += s1[x]; red[2] = s; }
    if (t == 64) { float s = 0.f; for (int y = 0; y < HW; y++) s += s2[y]; red[3] = s; }
    __syncthreads();
    if (t < HW)        g_att1[p*HW + t]        = s1[t]/red[2] + 1.f;
    else if (t < 2*HW) g_att2[p*HW + (t - HW)] = s2[t - HW]/red[3] + 1.f;
}

// proto pooling over x with att1, then l2norm over c; block = (b*NQ+q)*WAY + i
__global__ void __launch_bounds__(256) k_ppool() {
    int blk = blockIdx.x;
    int b = blk/(NQ*WAY); int rem = blk%(NQ*WAY); int q = rem/WAY; int i = rem%WAY;
    __shared__ float at[HW];
    __shared__ float red[256];
    __shared__ float rnv;
    int t = threadIdx.x;
    int p = (b*WAY + i)*NQ + q;
    if (t < HW) at[t] = g_att1[p*HW + t];
    __syncthreads();
    const float* pr = g_protos + (size_t)(b*WAY + i)*CHW;
    float v[2]; float sq = 0.f;
    #pragma unroll
    for (int r = 0; r < 2; r++) {
        int c = t + r*256;
        const float* row = pr + c*HW;
        float a = 0.f;
        #pragma unroll
        for (int x = 0; x < HW; x++) a += row[x]*at[x];
        v[r] = a*(1.f/36.f);
        sq += v[r]*v[r];
    }
    red[t] = sq; __syncthreads();
    for (int off = 128; off > 0; off >>= 1) {
        if (t < off) red[t] += red[t + off];
        __syncthreads();
    }
    if (t == 0) rnv = 1.f/fmaxf(sqrtf(red[0]), 1e-12f);
    __syncthreads();
    float* out = g_pnorm + (size_t)blk*CCH;
    #pragma unroll
    for (int r = 0; r < 2; r++) out[t + r*256] = v[r]*rnv;
}

// cls_scores[(b,q), i, x] = 7 * sum_c f2nT[b,q,x,c]*pnorm[b,q,i,c]
__global__ void k_cls(float* __restrict__ out2) {
    int bq = blockIdx.x;
    int t = threadIdx.x;
    if (t >= WAY*HW) return;
    int i = t/HW, x = t%HW;
    const float4* f2 = (const float4*)(g_f2nT  + ((size_t)bq*HW  + x)*CCH);
    const float4* pn = (const float4*)(g_pnorm + ((size_t)bq*WAY + i)*CCH);
    float a = 0.f;
    #pragma unroll 4
    for (int c = 0; c < CCH/4; c++) {
        float4 u = f2[c], w = pn[c];
        a += u.x*w.x + u.y*w.y + u.z*w.z + u.w*w.w;
    }
    out2[((size_t)bq*WAY + i)*HW + x] = 7.f*a;
}

// logits[(b,q),o,x] = (cls_w . query)[o,x] * attsel[x] + cls_b[o]
__global__ void __launch_bounds__(288) k_logit(const float* __restrict__ qf,
                                               const float* __restrict__ qt,
                                               const float* __restrict__ cw,
                                               const float* __restrict__ cb,
                                               float* __restrict__ out1) {
    int bq = blockIdx.x; int b = bq/NQ; int q = bq%NQ;
    __shared__ float qs[32][37];
    __shared__ float ws[64][33];
    __shared__ float asel[HW];
    int t  = threadIdx.x;          // 288
    int tx = t % HW;               // x
    int ty = t / HW;               // 0..7 (o group)
    if (t < HW) {
        float s = 0.f;
        #pragma unroll
        for (int i = 0; i < WAY; i++)
            s += g_att2[((b*WAY + i)*NQ + q)*HW + t] * qt[(size_t)bq*WAY + i];
        asel[t] = s;
    }
    float acc[8];
    #pragma unroll
    for (int k = 0; k < 8; k++) acc[k] = 0.f;
    const float* qbase = qf + (size_t)bq*CHW;
    for (int c0 = 0; c0 < CCH; c0 += 32) {
        for (int idx = t; idx < 32*HW; idx += 288) {
            int cc = idx/HW, x = idx%HW;
            qs[cc][x] = qbase[(c0 + cc)*HW + x];
        }
        for (int idx = t; idx < 64*32; idx += 288) {
            int o = idx >> 5, cc = idx & 31;
            ws[o][cc] = cw[o*CCH + c0 + cc];
        }
        __syncthreads();
        #pragma unroll 4
        for (int cc = 0; cc < 32; cc++) {
            float qv = qs[cc][tx];
            #pragma unroll
            for (int k = 0; k < 8; k++) acc[k] += ws[ty*8 + k][cc]*qv;
        }
        __syncthreads();
    }
    float av = asel[tx];
    #pragma unroll
    for (int k = 0; k < 8; k++) {
        int o = ty*8 + k;
        out1[((size_t)bq*NCLS + o)*HW + tx] = acc[k]*av + cb[o];
    }
}

// ---------------- launch ----------------
extern "C" void kernel_launch(void* const* d_in, const int* in_sizes, int n_in,
                              void* d_out, int out_size) {
    (void)in_sizes; (void)n_in; (void)out_size;
    const float* support = (const float*)d_in[0];
    const float* query   = (const float*)d_in[1];
    const float* st      = (const float*)d_in[2];
    const float* qt      = (const float*)d_in[3];
    const float* w1      = (const float*)d_in[4];
    const float* b1      = (const float*)d_in[5];
    const float* gam     = (const float*)d_in[6];
    const float* bet     = (const float*)d_in[7];
    const float* w2      = (const float*)d_in[8];
    const float* b2      = (const float*)d_in[9];
    const float* cw      = (const float*)d_in[10];
    const float* cb      = (const float*)d_in[11];
    float* out1 = (float*)d_out;                               // logits: 600*64*36
    float* out2 = out1 + (size_t)BB*NQ*NCLS*HW;                // cls_scores: 600*5*36

    k_zero  <<<1, 32>>>();
    k_protos<<<dim3(CHW/256, BB), 256>>>(support, st);
    k_norm1 <<<BB*WAY, 256>>>();
    k_norm2 <<<BB*NQ, 256>>>(query);
    k_gemm  <<<dim3((N_A + 63)/64, (M_A + 63)/64, BB), 256>>>();
    k_attpre<<<PAIRS, 128>>>(w1, b1);
    k_bnfin <<<1, 32>>>();
    k_att   <<<PAIRS, 128>>>(gam, bet, w2, b2);
    k_ppool <<<PAIRS, 256>>>();
    k_cls   <<<BB*NQ, 192>>>(out2);
    k_logit <<<BB*NQ, 288>>>(query, qt, cw, cb, out1);
}

// round 2
// speedup vs baseline: 1.8297x; 1.8297x over previous
#include <cuda_runtime.h>
#include <math.h>

#define BB   8
#define NS   25
#define NQ   75
#define WAY  5
#define CCH  512
#define HW   36
#define MID  6
#define NCLS 64
#define PAIRS (BB*WAY*NQ)   /* 3000 */
#define CHW  (CCH*HW)       /* 18432 */
#define NTOT (BB*NQ*HW)     /* 21600 */

// ---------------- scratch ----------------
__device__ float g_protos[BB*WAY*CHW];     // [b,i,c,x]
__device__ float g_rn1 [BB*WAY*HW];        // 1/||P[:,x]||
__device__ float g_mw1 [BB*WAY*CCH];       // (1/36) sum_x rn1[x] P[c,x]
__device__ float g_rn2 [BB*NQ*HW];
__device__ float g_mw2 [BB*NQ*CCH];
__device__ float g_yv  [2*PAIRS*MID];      // conv1 outputs path1,path2
__device__ float g_stats[24];              // [path][sum|sq][6]
__device__ float g_bnp  [24];              // [path][mu|istd][6]
__device__ float g_wv1 [PAIRS*HW];         // rn2[y]*aw1[y]
__device__ float g_wv2 [PAIRS*HW];         // rn1[x]*aw2[x]
__device__ float g_v1  [PAIRS*CCH];
__device__ float g_v2  [PAIRS*CCH];
__device__ float g_att1[PAIRS*HW];
__device__ float g_asel[BB*NQ*HW];         // sum_i att2[p_i,y]*qt[i]
__device__ float g_pnorm[BB*NQ*WAY*CCH];

__global__ void k_zero() {
    int t = threadIdx.x;
    if (t < 24) g_stats[t] = 0.f;
}

// prototypes
__global__ void k_protos(const float* __restrict__ sup, const float* __restrict__ st) {
    int b = blockIdx.y;
    int t = threadIdx.x;
    __shared__ float sts[NS*WAY];
    __shared__ float cnt[WAY];
    if (t < NS*WAY) sts[t] = st[b*NS*WAY + t];
    __syncthreads();
    if (t < WAY) { float s = 0.f; for (int n = 0; n < NS; n++) s += sts[n*WAY + t]; cnt[t] = s; }
    __syncthreads();
    int d = blockIdx.x*256 + t;
    if (d >= CHW) return;
    float acc[WAY] = {0.f,0.f,0.f,0.f,0.f};
    const float* sb = sup + (size_t)b*NS*CHW + d;
    for (int n = 0; n < NS; n++) {
        float v = sb[(size_t)n*CHW];
        #pragma unroll
        for (int w = 0; w < WAY; w++) acc[w] += sts[n*WAY + w]*v;
    }
    #pragma unroll
    for (int w = 0; w < WAY; w++)
        g_protos[(size_t)(b*WAY + w)*CHW + d] = acc[w]/cnt[w];
}

// per (b,i): rn1[x], mw1[c]
__global__ void __launch_bounds__(288) k_prep1() {
    int bi = blockIdx.x;
    const float* P = g_protos + (size_t)bi*CHW;
    __shared__ float part[288];
    __shared__ float rn1s[HW];
    int t = threadIdx.x;
    float sq = 0.f;
    for (int e = t; e < CHW; e += 288) { float v = P[e]; sq += v*v; }
    part[t] = sq; __syncthreads();
    if (t < HW) {
        float s = 0.f;
        #pragma unroll
        for (int g = 0; g < 8; g++) s += part[g*HW + t];
        float r = 1.f/fmaxf(sqrtf(s), 1e-12f);
        rn1s[t] = r; g_rn1[bi*HW + t] = r;
    }
    __syncthreads();
    for (int c = t; c < CCH; c += 288) {
        const float* row = P + c*HW;
        float a = 0.f;
        #pragma unroll
        for (int x = 0; x < HW; x++) a += row[x]*rn1s[x];
        g_mw1[bi*CCH + c] = a*(1.f/36.f);
    }
}

// per (b,q): rn2[y], mw2[c]
__global__ void __launch_bounds__(288) k_prep2(const float* __restrict__ Q) {
    int bq = blockIdx.x;
    const float* Qb = Q + (size_t)bq*CHW;
    __shared__ float part[288];
    __shared__ float rn2s[HW];
    int t = threadIdx.x;
    float sq = 0.f;
    for (int e = t; e < CHW; e += 288) { float v = Qb[e]; sq += v*v; }
    part[t] = sq; __syncthreads();
    if (t < HW) {
        float s = 0.f;
        #pragma unroll
        for (int g = 0; g < 8; g++) s += part[g*HW + t];
        float r = 1.f/fmaxf(sqrtf(s), 1e-12f);
        rn2s[t] = r; g_rn2[bq*HW + t] = r;
    }
    __syncthreads();
    for (int c = t; c < CCH; c += 288) {
        const float* row = Qb + c*HW;
        float a = 0.f;
        #pragma unroll
        for (int y = 0; y < HW; y++) a += row[y]*rn2s[y];
        g_mw2[bq*CCH + c] = a*(1.f/36.f);
    }
}

// path1 conv input + conv1 + BN stats; per (b,q), streams Q once
__global__ void __launch_bounds__(288) k_ch1(const float* __restrict__ Q,
                                             const float* __restrict__ w1,
                                             const float* __restrict__ b1) {
    int bq = blockIdx.x; int b = bq/NQ, q = bq%NQ;
    __shared__ float mw1s[WAY][CCH];
    __shared__ float red[WAY][288];
    __shared__ float ch1s[WAY][HW];
    int t = threadIdx.x;
    for (int idx = t; idx < WAY*CCH; idx += 288)
        mw1s[idx/CCH][idx%CCH] = g_mw1[b*WAY*CCH + idx];
    __syncthreads();
    float a0=0.f,a1a=0.f,a2=0.f,a3=0.f,a4=0.f;
    const float* Qb = Q + (size_t)bq*CHW;
    int c = t/36;
    for (int e = t; e < CHW; e += 288, c += 8) {
        float v = Qb[e];
        a0 += mw1s[0][c]*v; a1a += mw1s[1][c]*v; a2 += mw1s[2][c]*v;
        a3 += mw1s[3][c]*v; a4 += mw1s[4][c]*v;
    }
    red[0][t]=a0; red[1][t]=a1a; red[2][t]=a2; red[3][t]=a3; red[4][t]=a4;
    __syncthreads();
    if (t < WAY*HW) {
        int i = t/HW, y = t%HW;
        float s = 0.f;
        #pragma unroll
        for (int g = 0; g < 8; g++) s += red[i][g*HW + y];
        ch1s[i][y] = s * g_rn2[bq*HW + y];
    }
    __syncthreads();
    if (t < WAY*MID) {
        int i = t/MID, m = t%MID;
        float a = b1[m];
        #pragma unroll
        for (int y = 0; y < HW; y++) a += w1[m*HW + y]*ch1s[i][y];
        int p = (b*WAY + i)*NQ + q;
        g_yv[p*MID + m] = a;
        atomicAdd(&g_stats[m], a); atomicAdd(&g_stats[MID + m], a*a);
    }
}

// path2 conv input + conv1 + BN stats; per (b,i, q-chunk16)
__global__ void __launch_bounds__(288) k_ch2(const float* __restrict__ w1,
                                             const float* __restrict__ b1) {
    int bi = blockIdx.x; int qc = blockIdx.y*16;
    int b = bi/WAY, i = bi%WAY;
    const float* P = g_protos + (size_t)bi*CHW;
    __shared__ float rn1s[HW];
    __shared__ float mw2s[16][CCH];
    __shared__ float ch2s[16][HW];
    int t = threadIdx.x;
    if (t < HW) rn1s[t] = g_rn1[bi*HW + t];
    for (int idx = t; idx < 16*CCH; idx += 288) {
        int qq = qc + idx/CCH;
        mw2s[idx/CCH][idx%CCH] = (qq < NQ) ? g_mw2[(b*NQ + qq)*CCH + idx%CCH] : 0.f;
    }
    __syncthreads();
    int qg = t/HW, x = t%HW;
    float acc0 = 0.f, acc1 = 0.f;
    for (int cc = 0; cc < CCH; cc++) {
        float pv = P[cc*HW + x];
        acc0 += mw2s[qg][cc]*pv;
        acc1 += mw2s[qg+8][cc]*pv;
    }
    ch2s[qg][x]   = acc0*rn1s[x];
    ch2s[qg+8][x] = acc1*rn1s[x];
    __syncthreads();
    if (t < 16*MID) {
        int g2 = t/MID, m = t%MID; int q2 = qc + g2;
        if (q2 < NQ) {
            float s = b1[m];
            #pragma unroll
            for (int xx = 0; xx < HW; xx++) s += w1[m*HW + xx]*ch2s[g2][xx];
            int p = (b*WAY + i)*NQ + q2;
            g_yv[PAIRS*MID + p*MID + m] = s;
            atomicAdd(&g_stats[2*MID + m], s); atomicAdd(&g_stats[3*MID + m], s*s);
        }
    }
}

__global__ void k_bnfin() {
    int t = threadIdx.x;
    if (t < 12) {
        int path = t/MID, m = t%MID;
        float sum = g_stats[path*12 + m];
        float sq  = g_stats[path*12 + MID + m];
        float mu  = sum/(float)PAIRS;
        float var = sq/(float)PAIRS - mu*mu;
        g_bnp[path*12 + m]       = mu;
        g_bnp[path*12 + MID + m] = rsqrtf(var + 1e-5f);
    }
}

// BN+relu+conv2 -> wv1 (rn2*aw1), wv2 (rn1*aw2); 4 pairs per block
__global__ void __launch_bounds__(288) k_aw(const float* __restrict__ gam,
                                            const float* __restrict__ bet,
                                            const float* __restrict__ w2,
                                            const float* __restrict__ b2,
                                            const float* __restrict__ qtdummy) {
    (void)qtdummy;
    __shared__ float h[4][12];
    int t = threadIdx.x;
    int sub = t/72, tt = t%72;
    int p = blockIdx.x*4 + sub;
    int b = p/(WAY*NQ); int rem = p%(WAY*NQ); int i = rem/NQ; int q = rem%NQ;
    int bq = b*NQ + q;
    if (tt < 12) {
        int path = tt/MID, m = tt%MID;
        float v   = g_yv[path*PAIRS*MID + p*MID + m];
        float mu  = g_bnp[path*12 + m];
        float ist = g_bnp[path*12 + MID + m];
        float z = gam[m]*(v - mu)*ist + bet[m];
        h[sub][tt] = fmaxf(z, 0.f);
    }
    __syncthreads();
    int path = tt/HW, k = tt%HW;
    float a = b2[k];
    #pragma unroll
    for (int m = 0; m < MID; m++) a += w2[k*MID + m]*h[sub][path*MID + m];
    if (path == 0) g_wv1[p*HW + k] = a * g_rn2[bq*HW + k];
    else           g_wv2[p*HW + k] = a * g_rn1[(b*WAY + i)*HW + k];
}

// v1[p,c] = sum_y Q[c,y]*wv1[p,y]; per (b,q), 5 pairs
__global__ void __launch_bounds__(288) k_v1(const float* __restrict__ Q) {
    int bq = blockIdx.x; int b = bq/NQ, q = bq%NQ;
    __shared__ float wv1s[WAY][HW];
    int t = threadIdx.x;
    if (t < WAY*HW) wv1s[t/HW][t%HW] = g_wv1[((b*WAY + t/HW)*NQ + q)*HW + t%HW];
    __syncthreads();
    const float* Qb = Q + (size_t)bq*CHW;
    for (int c = t; c < CCH; c += 288) {
        float row[HW];
        const float* r = Qb + c*HW;
        #pragma unroll
        for (int y = 0; y < HW; y++) row[y] = r[y];
        #pragma unroll
        for (int i = 0; i < WAY; i++) {
            float a = 0.f;
            #pragma unroll
            for (int y = 0; y < HW; y++) a += row[y]*wv1s[i][y];
            g_v1[(size_t)((b*WAY + i)*NQ + q)*CCH + c] = a;
        }
    }
}

// v2[p,c] = sum_x P[b,i,c,x]*wv2[p,x]; per (b,i, q-chunk25)
__global__ void __launch_bounds__(288) k_v2() {
    int bi = blockIdx.x; int qc = blockIdx.y*25;
    int b = bi/WAY, i = bi%WAY;
    const float* P = g_protos + (size_t)bi*CHW;
    __shared__ float wv2s[25][HW];
    int t = threadIdx.x;
    for (int idx = t; idx < 25*HW; idx += 288) {
        int qq = qc + idx/HW;
        wv2s[idx/HW][idx%HW] = (qq < NQ) ? g_wv2[((b*WAY + i)*NQ + qq)*HW + idx%HW] : 0.f;
    }
    __syncthreads();
    for (int c = t; c < CCH; c += 288) {
        float row[HW];
        const float* r = P + c*HW;
        #pragma unroll
        for (int x = 0; x < HW; x++) row[x] = r[x];
        for (int qq = 0; qq < 25; qq++) {
            if (qc + qq >= NQ) break;
            float a = 0.f;
            #pragma unroll
            for (int x = 0; x < HW; x++) a += row[x]*wv2s[qq][x];
            g_v2[(size_t)((b*WAY + i)*NQ + qc + qq)*CCH + c] = a;
        }
    }
}

// s1 + softmax -> att1; per (b,i, q-chunk16)
__global__ void __launch_bounds__(288) k_s1() {
    int bi = blockIdx.x; int qc = blockIdx.y*16;
    int b = bi/WAY, i = bi%WAY;
    const float* P = g_protos + (size_t)bi*CHW;
    __shared__ float v1s[16][CCH];
    __shared__ float sblk[16][HW];
    __shared__ float rn1s[HW];
    __shared__ float mx[16], sm[16];
    int t = threadIdx.x;
    if (t < HW) rn1s[t] = g_rn1[bi*HW + t];
    for (int idx = t; idx < 16*CCH; idx += 288) {
        int qq = qc + idx/CCH;
        v1s[idx/CCH][idx%CCH] = (qq < NQ) ?
            g_v1[(size_t)((b*WAY + i)*NQ + qq)*CCH + idx%CCH] : 0.f;
    }
    __syncthreads();
    int qg = t/HW, x = t%HW;
    float acc0 = 0.f, acc1 = 0.f;
    for (int cc = 0; cc < CCH; cc++) {
        float pv = P[cc*HW + x];
        acc0 += v1s[qg][cc]*pv;
        acc1 += v1s[qg+8][cc]*pv;
    }
    sblk[qg][x]   = acc0*rn1s[x]*(1.f/36.f);
    sblk[qg+8][x] = acc1*rn1s[x]*(1.f/36.f);
    __syncthreads();
    if (t < 16) {
        float m = -1e30f;
        #pragma unroll
        for (int xx = 0; xx < HW; xx++) m = fmaxf(m, sblk[t][xx]);
        mx[t] = m;
    }
    __syncthreads();
    sblk[qg][x]   = expf((sblk[qg][x]   - mx[qg])*40.f);
    sblk[qg+8][x] = expf((sblk[qg+8][x] - mx[qg+8])*40.f);
    __syncthreads();
    if (t < 16) {
        float s = 0.f;
        #pragma unroll
        for (int xx = 0; xx < HW; xx++) s += sblk[t][xx];
        sm[t] = s;
    }
    __syncthreads();
    #pragma unroll
    for (int r = 0; r < 2; r++) {
        int qrow = qg + r*8;
        int q2 = qc + qrow;
        if (q2 < NQ)
            g_att1[((b*WAY + i)*NQ + q2)*HW + x] = sblk[qrow][x]/sm[qrow] + 1.f;
    }
}

// s2 + softmax + attsel; per (b,q) streaming Q
__global__ void __launch_bounds__(288) k_s2(const float* __restrict__ Q,
                                            const float* __restrict__ qt) {
    int bq = blockIdx.x; int b = bq/NQ, q = bq%NQ;
    __shared__ float v2s[WAY][CCH];
    __shared__ float red[WAY][288];
    __shared__ float s2s[WAY][HW];
    __shared__ float mx[WAY], sm[WAY];
    int t = threadIdx.x;
    #pragma unroll
    for (int i = 0; i < WAY; i++)
        for (int idx = t; idx < CCH; idx += 288)
            v2s[i][idx] = g_v2[(size_t)((b*WAY + i)*NQ + q)*CCH + idx];
    __syncthreads();
    float a0=0.f,a1a=0.f,a2=0.f,a3=0.f,a4=0.f;
    const float* Qb = Q + (size_t)bq*CHW;
    int c = t/36;
    for (int e = t; e < CHW; e += 288, c += 8) {
        float v = Qb[e];
        a0 += v2s[0][c]*v; a1a += v2s[1][c]*v; a2 += v2s[2][c]*v;
        a3 += v2s[3][c]*v; a4 += v2s[4][c]*v;
    }
    red[0][t]=a0; red[1][t]=a1a; red[2][t]=a2; red[3][t]=a3; red[4][t]=a4;
    __syncthreads();
    if (t < WAY*HW) {
        int i = t/HW, y = t%HW;
        float s = 0.f;
        #pragma unroll
        for (int g = 0; g < 8; g++) s += red[i][g*HW + y];
        s2s[i][y] = s * g_rn2[bq*HW + y] * (1.f/36.f);
    }
    __syncthreads();
    if (t < WAY) {
        float m = -1e30f;
        #pragma unroll
        for (int yy = 0; yy < HW; yy++) m = fmaxf(m, s2s[t][yy]);
        mx[t] = m;
    }
    __syncthreads();
    if (t < WAY*HW) {
        int i = t/HW, y = t%HW;
        s2s[i][y] = expf((s2s[i][y] - mx[i])*40.f);
    }
    __syncthreads();
    if (t < WAY) {
        float s = 0.f;
        #pragma unroll
        for (int yy = 0; yy < HW; yy++) s += s2s[t][yy];
        sm[t] = s;
    }
    __syncthreads();
    if (t < HW) {
        float a = 0.f;
        #pragma unroll
        for (int i = 0; i < WAY; i++)
            a += (s2s[i][t]/sm[i] + 1.f) * qt[(size_t)bq*WAY + i];
        g_asel[bq*HW + t] = a;
    }
}

// proto pooling + l2norm; per (bq,i)
__global__ void __launch_bounds__(256) k_ppool() {
    int blk = blockIdx.x;
    int b = blk/(NQ*WAY); int rem = blk%(NQ*WAY); int q = rem/WAY; int i = rem%WAY;
    __shared__ float at[HW];
    __shared__ float red[256];
    __shared__ float rnv;
    int t = threadIdx.x;
    int p = (b*WAY + i)*NQ + q;
    if (t < HW) at[t] = g_att1[p*HW + t];
    __syncthreads();
    const float* pr = g_protos + (size_t)(b*WAY + i)*CHW;
    float v[2]; float sq = 0.f;
    #pragma unroll
    for (int r = 0; r < 2; r++) {
        int c = t + r*256;
        const float* row = pr + c*HW;
        float a = 0.f;
        #pragma unroll
        for (int x = 0; x < HW; x++) a += row[x]*at[x];
        v[r] = a*(1.f/36.f);
        sq += v[r]*v[r];
    }
    red[t] = sq; __syncthreads();
    for (int off = 128; off > 0; off >>= 1) {
        if (t < off) red[t] += red[t + off];
        __syncthreads();
    }
    if (t == 0) rnv = 1.f/fmaxf(sqrtf(red[0]), 1e-12f);
    __syncthreads();
    float* out = g_pnorm + (size_t)blk*CCH;
    #pragma unroll
    for (int r = 0; r < 2; r++) out[t + r*256] = v[r]*rnv;
}

// cls_scores: per (b,q) streaming Q with pnorm in smem
__global__ void __launch_bounds__(288) k_cls(const float* __restrict__ Q,
                                             float* __restrict__ out2) {
    int bq = blockIdx.x;
    __shared__ float pn[WAY][CCH];
    __shared__ float red[WAY][288];
    int t = threadIdx.x;
    for (int idx = t; idx < WAY*CCH; idx += 288)
        pn[idx/CCH][idx%CCH] = g_pnorm[(size_t)bq*WAY*CCH + idx];
    __syncthreads();
    float a0=0.f,a1a=0.f,a2=0.f,a3=0.f,a4=0.f;
    const float* Qb = Q + (size_t)bq*CHW;
    int c = t/36;
    for (int e = t; e < CHW; e += 288, c += 8) {
        float v = Qb[e];
        a0 += pn[0][c]*v; a1a += pn[1][c]*v; a2 += pn[2][c]*v;
        a3 += pn[3][c]*v; a4 += pn[4][c]*v;
    }
    red[0][t]=a0; red[1][t]=a1a; red[2][t]=a2; red[3][t]=a3; red[4][t]=a4;
    __syncthreads();
    if (t < WAY*HW) {
        int i = t/HW, x = t%HW;
        float s = 0.f;
        #pragma unroll
        for (int g = 0; g < 8; g++) s += red[i][g*HW + x];
        out2[((size_t)bq*WAY + i)*HW + x] = 7.f * g_rn2[bq*HW + x] * s;
    }
}

// logits: C[64 x 21600] = cls_w[64x512] * Qall, epilogue *asel + cb
__global__ void __launch_bounds__(128) k_logit(const float* __restrict__ Q,
                                               const float* __restrict__ cw,
                                               const float* __restrict__ cb,
                                               float* __restrict__ out1) {
    int n0 = blockIdx.x*64;
    int t = threadIdx.x;
    int tn = t & 15, tm = t >> 4;          // tm<8
    __shared__ float As[16][72];           // [k][o]
    __shared__ float Bs[16][68];           // [k][nn]
    int nn_l = t & 63, kgrp = t >> 6;      // kgrp in {0,1}
    int nglob = n0 + nn_l;
    bool nval = nglob < NTOT;
    int bq_l = nval ? nglob/36 : 0;
    int x_l  = nval ? nglob%36 : 0;
    const float* qbase = Q + (size_t)bq_l*CHW + x_l;
    int o_a = t >> 1, ka = (t & 1)*8;
    float acc[8][4];
    #pragma unroll
    for (int r = 0; r < 8; r++)
        #pragma unroll
        for (int j = 0; j < 4; j++) acc[r][j] = 0.f;
    for (int k0 = 0; k0 < CCH; k0 += 16) {
        float4 av0 = *(const float4*)(cw + o_a*CCH + k0 + ka);
        float4 av1 = *(const float4*)(cw + o_a*CCH + k0 + ka + 4);
        As[ka+0][o_a] = av0.x; As[ka+1][o_a] = av0.y;
        As[ka+2][o_a] = av0.z; As[ka+3][o_a] = av0.w;
        As[ka+4][o_a] = av1.x; As[ka+5][o_a] = av1.y;
        As[ka+6][o_a] = av1.z; As[ka+7][o_a] = av1.w;
        #pragma unroll
        for (int j = 0; j < 8; j++) {
            int kk = kgrp*8 + j;
            Bs[kk][nn_l] = nval ? qbase[(size_t)(k0 + kk)*HW] : 0.f;
        }
        __syncthreads();
        #pragma unroll
        for (int k = 0; k < 16; k++) {
            float4 af0 = *(const float4*)&As[k][tm*8];
            float4 af1 = *(const float4*)&As[k][tm*8 + 4];
            float4 bf  = *(const float4*)&Bs[k][tn*4];
            float am[8] = {af0.x,af0.y,af0.z,af0.w,af1.x,af1.y,af1.z,af1.w};
            float bn[4] = {bf.x,bf.y,bf.z,bf.w};
            #pragma unroll
            for (int r = 0; r < 8; r++)
                #pragma unroll
                for (int j = 0; j < 4; j++) acc[r][j] += am[r]*bn[j];
        }
        __syncthreads();
    }
    #pragma unroll
    for (int j = 0; j < 4; j++) {
        int n = n0 + tn*4 + j;
        if (n >= NTOT) continue;
        int bq = n/36, x = n%36;
        float av = g_asel[n];
        #pragma unroll
        for (int r = 0; r < 8; r++) {
            int o = tm*8 + r;
            out1[((size_t)bq*NCLS + o)*HW + x] = acc[r][j]*av + cb[o];
        }
    }
}

// ---------------- launch ----------------
extern "C" void kernel_launch(void* const* d_in, const int* in_sizes, int n_in,
                              void* d_out, int out_size) {
    (void)in_sizes; (void)n_in; (void)out_size;
    const float* support = (const float*)d_in[0];
    const float* query   = (const float*)d_in[1];
    const float* st      = (const float*)d_in[2];
    const float* qt      = (const float*)d_in[3];
    const float* w1      = (const float*)d_in[4];
    const float* b1      = (const float*)d_in[5];
    const float* gam     = (const float*)d_in[6];
    const float* bet     = (const float*)d_in[7];
    const float* w2      = (const float*)d_in[8];
    const float* b2      = (const float*)d_in[9];
    const float* cw      = (const float*)d_in[10];
    const float* cb      = (const float*)d_in[11];
    float* out1 = (float*)d_out;                               // logits 600*64*36
    float* out2 = out1 + (size_t)BB*NQ*NCLS*HW;                // cls_scores 600*5*36

    k_zero  <<<1, 32>>>();
    k_protos<<<dim3(CHW/256, BB), 256>>>(support, st);
    k_prep1 <<<BB*WAY, 288>>>();
    k_prep2 <<<BB*NQ, 288>>>(query);
    k_ch1   <<<BB*NQ, 288>>>(query, w1, b1);
    k_ch2   <<<dim3(BB*WAY, 5), 288>>>(w1, b1);
    k_bnfin <<<1, 32>>>();
    k_aw    <<<PAIRS/4, 288>>>(gam, bet, w2, b2, qt);
    k_v1    <<<BB*NQ, 288>>>(query);
    k_v2    <<<dim3(BB*WAY, 3), 288>>>();
    k_s1    <<<dim3(BB*WAY, 5), 288>>>();
    k_s2    <<<BB*NQ, 288>>>(query, qt);
    k_ppool <<<PAIRS, 256>>>();
    k_cls   <<<BB*NQ, 288>>>(query, out2);
    k_logit <<<(NTOT + 63)/64, 128>>>(query, cw, cb, out1);
}

// round 3
// speedup vs baseline: 2.2784x; 1.2452x over previous
#include <cuda_runtime.h>
#include <math.h>

#define BB   8
#define NS   25
#define NQ   75
#define WAY  5
#define CCH  512
#define HW   36
#define MID  6
#define NCLS 64
#define PAIRS (BB*WAY*NQ)   /* 3000 */
#define CHW  (CCH*HW)       /* 18432 */
#define CHW4 (CHW/4)        /* 4608 */
#define NTOT (BB*NQ*HW)     /* 21600 */

// ---------------- scratch ----------------
__device__ float g_protos[BB*WAY*CHW];     // [b,i,c,x]
__device__ float g_rn1 [BB*WAY*HW];
__device__ float g_mw1 [BB*WAY*CCH];
__device__ float g_rn2 [BB*NQ*HW];
__device__ float g_mw2 [BB*NQ*CCH];
__device__ float g_yv  [2*PAIRS*MID];
__device__ float g_stats[24];
__device__ float g_wv1 [PAIRS*HW];
__device__ float g_wv2 [PAIRS*HW];
__device__ float g_v1  [PAIRS*CCH];        // v1, later overwritten with pooled protos
__device__ float g_v2  [PAIRS*CCH];
__device__ float g_asel[BB*NQ*HW];
__device__ float g_pnf [PAIRS];            // 1/||pooled||

// prototypes (float4) + zero stats
__global__ void __launch_bounds__(288) k_protos(const float* __restrict__ sup,
                                                const float* __restrict__ st) {
    int b = blockIdx.y, t = threadIdx.x;
    if (blockIdx.x == 0 && b == 0 && t < 24) g_stats[t] = 0.f;
    __shared__ float sts[NS*WAY];
    __shared__ float rcnt[WAY];
    if (t < NS*WAY) sts[t] = st[b*NS*WAY + t];
    __syncthreads();
    if (t < WAY) { float s = 0.f; for (int n = 0; n < NS; n++) s += sts[n*WAY + t]; rcnt[t] = 1.f/s; }
    __syncthreads();
    int d4 = blockIdx.x*288 + t;           // grid.x = 16, 16*288 = 4608
    const float4* sb = (const float4*)sup + (size_t)b*NS*CHW4 + d4;
    float4 acc[WAY];
    #pragma unroll
    for (int w = 0; w < WAY; w++) acc[w] = make_float4(0.f,0.f,0.f,0.f);
    for (int n = 0; n < NS; n++) {
        float4 v = sb[(size_t)n*CHW4];
        #pragma unroll
        for (int w = 0; w < WAY; w++) {
            float s = sts[n*WAY + w];
            acc[w].x += s*v.x; acc[w].y += s*v.y; acc[w].z += s*v.z; acc[w].w += s*v.w;
        }
    }
    #pragma unroll
    for (int w = 0; w < WAY; w++) {
        float r = rcnt[w];
        float4 o = make_float4(acc[w].x*r, acc[w].y*r, acc[w].z*r, acc[w].w*r);
        ((float4*)g_protos)[(size_t)(b*WAY + w)*CHW4 + d4] = o;
    }
}

// per (b,i): rn1, mw1
__global__ void __launch_bounds__(288) k_prep1() {
    int bi = blockIdx.x, t = threadIdx.x;
    const float4* P4 = (const float4*)(g_protos + (size_t)bi*CHW);
    __shared__ float part[288*4];
    __shared__ float rn1s[HW];
    float s0=0.f,s1=0.f,s2=0.f,s3=0.f;
    #pragma unroll 4
    for (int k = 0; k < 16; k++) {
        float4 v = P4[t + 288*k];
        s0 += v.x*v.x; s1 += v.y*v.y; s2 += v.z*v.z; s3 += v.w*v.w;
    }
    part[4*t]=s0; part[4*t+1]=s1; part[4*t+2]=s2; part[4*t+3]=s3;
    __syncthreads();
    if (t < HW) {
        int y4 = t >> 2, j = t & 3;
        float s = 0.f;
        #pragma unroll
        for (int m = 0; m < 32; m++) s += part[4*(y4 + 9*m) + j];
        float r = 1.f/fmaxf(sqrtf(s), 1e-12f);
        rn1s[t] = r; g_rn1[bi*HW + t] = r;
    }
    __syncthreads();
    for (int c = t; c < CCH; c += 288) {
        const float4* row = P4 + c*9;
        float a = 0.f;
        #pragma unroll
        for (int y4 = 0; y4 < 9; y4++) {
            float4 v = row[y4];
            a += v.x*rn1s[y4*4] + v.y*rn1s[y4*4+1] + v.z*rn1s[y4*4+2] + v.w*rn1s[y4*4+3];
        }
        g_mw1[bi*CCH + c] = a*(1.f/36.f);
    }
}

// fused prep2 + ch1: per bq, one DRAM pass over Q (+L1 re-pass for mw2)
__global__ void __launch_bounds__(288) k_prep2ch1(const float* __restrict__ Q,
                                                  const float* __restrict__ w1,
                                                  const float* __restrict__ b1) {
    int bq = blockIdx.x; int b = bq/NQ, q = bq%NQ;
    int t = threadIdx.x;
    __shared__ float mw1s[WAY*CCH];
    __shared__ float redA[20][288];
    __shared__ float part[288*4];
    __shared__ float rn2s[HW];
    __shared__ float ch1s[WAY][HW];
    {
        const float4* src = (const float4*)(g_mw1 + b*WAY*CCH);
        float4* dst = (float4*)mw1s;
        for (int i4 = t; i4 < WAY*CCH/4; i4 += 288) dst[i4] = src[i4];
    }
    __syncthreads();
    const float4* Q4 = (const float4*)(Q + (size_t)bq*CHW);
    float aacc[WAY][4];
    float sq[4] = {0.f,0.f,0.f,0.f};
    #pragma unroll
    for (int i = 0; i < WAY; i++)
        #pragma unroll
        for (int j = 0; j < 4; j++) aacc[i][j] = 0.f;
    #pragma unroll 2
    for (int k = 0; k < 16; k++) {
        int idx = t + 288*k;
        int c = idx/9;
        float4 v = Q4[idx];
        sq[0] += v.x*v.x; sq[1] += v.y*v.y; sq[2] += v.z*v.z; sq[3] += v.w*v.w;
        #pragma unroll
        for (int i = 0; i < WAY; i++) {
            float w = mw1s[i*CCH + c];
            aacc[i][0] += w*v.x; aacc[i][1] += w*v.y; aacc[i][2] += w*v.z; aacc[i][3] += w*v.w;
        }
    }
    #pragma unroll
    for (int j = 0; j < 4; j++) part[4*t + j] = sq[j];
    #pragma unroll
    for (int i = 0; i < WAY; i++)
        #pragma unroll
        for (int j = 0; j < 4; j++) redA[i*4 + j][t] = aacc[i][j];
    __syncthreads();
    if (t < HW) {
        int y4 = t >> 2, j = t & 3;
        float s = 0.f;
        #pragma unroll
        for (int m = 0; m < 32; m++) s += part[4*(y4 + 9*m) + j];
        float r = 1.f/fmaxf(sqrtf(s), 1e-12f);
        rn2s[t] = r; g_rn2[bq*HW + t] = r;
    }
    __syncthreads();
    if (t < WAY*HW) {
        int i = t/HW, y = t%HW;
        int y4 = y >> 2, j = y & 3;
        float s = 0.f;
        #pragma unroll
        for (int m = 0; m < 32; m++) s += redA[i*4 + j][y4 + 9*m];
        ch1s[i][y] = s*rn2s[y];
    }
    // pass2: mw2 (Q rows now L1-resident)
    for (int c = t; c < CCH; c += 288) {
        const float4* row = Q4 + c*9;
        float a = 0.f;
        #pragma unroll
        for (int y4 = 0; y4 < 9; y4++) {
            float4 v = row[y4];
            a += v.x*rn2s[y4*4] + v.y*rn2s[y4*4+1] + v.z*rn2s[y4*4+2] + v.w*rn2s[y4*4+3];
        }
        g_mw2[bq*CCH + c] = a*(1.f/36.f);
    }
    __syncthreads();
    if (t < WAY*MID) {
        int i = t/MID, m = t%MID;
        float a = b1[m];
        #pragma unroll
        for (int y = 0; y < HW; y++) a += w1[m*HW + y]*ch1s[i][y];
        int p = (b*WAY + i)*NQ + q;
        g_yv[p*MID + m] = a;
        atomicAdd(&g_stats[m], a); atomicAdd(&g_stats[MID + m], a*a);
    }
}

// path2 conv input + conv1 + BN stats; per (b,i, q-chunk16)
__global__ void __launch_bounds__(288) k_ch2(const float* __restrict__ w1,
                                             const float* __restrict__ b1) {
    int bi = blockIdx.x; int qc = blockIdx.y*16;
    int b = bi/WAY, i = bi%WAY;
    const float* P = g_protos + (size_t)bi*CHW;
    __shared__ float rn1s[HW];
    __shared__ float mw2s[16][CCH];
    __shared__ float ch2s[16][HW];
    int t = threadIdx.x;
    if (t < HW) rn1s[t] = g_rn1[bi*HW + t];
    for (int idx = t; idx < 16*CCH; idx += 288) {
        int qq = qc + idx/CCH;
        mw2s[idx/CCH][idx%CCH] = (qq < NQ) ? g_mw2[(b*NQ + qq)*CCH + idx%CCH] : 0.f;
    }
    __syncthreads();
    int qg = t/HW, x = t%HW;
    float acc0 = 0.f, acc1 = 0.f;
    for (int cc = 0; cc < CCH; cc++) {
        float pv = P[cc*HW + x];
        acc0 += mw2s[qg][cc]*pv;
        acc1 += mw2s[qg+8][cc]*pv;
    }
    ch2s[qg][x]   = acc0*rn1s[x];
    ch2s[qg+8][x] = acc1*rn1s[x];
    __syncthreads();
    if (t < 16*MID) {
        int g2 = t/MID, m = t%MID; int q2 = qc + g2;
        if (q2 < NQ) {
            float s = b1[m];
            #pragma unroll
            for (int xx = 0; xx < HW; xx++) s += w1[m*HW + xx]*ch2s[g2][xx];
            int p = (b*WAY + i)*NQ + q2;
            g_yv[PAIRS*MID + p*MID + m] = s;
            atomicAdd(&g_stats[2*MID + m], s); atomicAdd(&g_stats[3*MID + m], s*s);
        }
    }
}

// BN finalize (local) + BN+relu+conv2 -> wv1, wv2; 4 pairs per block
__global__ void __launch_bounds__(288) k_aw(const float* __restrict__ gam,
                                            const float* __restrict__ bet,
                                            const float* __restrict__ w2,
                                            const float* __restrict__ b2) {
    __shared__ float h[4][12];
    __shared__ float bnps[24];
    int t = threadIdx.x;
    if (t < 12) {
        int path = t/MID, m = t%MID;
        float sum = g_stats[path*12 + m];
        float sqs = g_stats[path*12 + MID + m];
        float mu  = sum/(float)PAIRS;
        float var = sqs/(float)PAIRS - mu*mu;
        bnps[path*12 + m]       = mu;
        bnps[path*12 + MID + m] = rsqrtf(var + 1e-5f);
    }
    __syncthreads();
    int sub = t/72, tt = t%72;
    int p = blockIdx.x*4 + sub;
    int b = p/(WAY*NQ); int rem = p%(WAY*NQ); int i = rem/NQ; int q = rem%NQ;
    int bq = b*NQ + q;
    if (tt < 12) {
        int path = tt/MID, m = tt%MID;
        float v   = g_yv[path*PAIRS*MID + p*MID + m];
        float mu  = bnps[path*12 + m];
        float ist = bnps[path*12 + MID + m];
        float z = gam[m]*(v - mu)*ist + bet[m];
        h[sub][tt] = fmaxf(z, 0.f);
    }
    __syncthreads();
    int path = tt/HW, k = tt%HW;
    float a = b2[k];
    #pragma unroll
    for (int m = 0; m < MID; m++) a += w2[k*MID + m]*h[sub][path*MID + m];
    if (path == 0) g_wv1[p*HW + k] = a * g_rn2[bq*HW + k];
    else           g_wv2[p*HW + k] = a * g_rn1[(b*WAY + i)*HW + k];
}

// v2[p,c] = sum_x P[c,x]*wv2[p,x]; per (b,i, q-chunk25); smem-tiled
__global__ void __launch_bounds__(288) k_v2() {
    int bi = blockIdx.x; int qc = blockIdx.y*25;   // 3*25 = 75 exact
    int pb = bi*NQ + qc;
    const float* P = g_protos + (size_t)bi*CHW;
    __shared__ float wv2s[25*HW];
    __shared__ float tile[32*37];
    int t = threadIdx.x;
    for (int idx = t; idx < 25*HW; idx += 288) wv2s[idx] = g_wv2[pb*HW + idx];
    __syncthreads();
    int x = t%36, trow = t/36;
    for (int c0 = 0; c0 < CCH; c0 += 32) {
        #pragma unroll
        for (int j = 0; j < 4; j++)
            tile[(trow + 8*j)*37 + x] = P[(c0 + trow + 8*j)*HW + x];
        __syncthreads();
        #pragma unroll
        for (int r = 0; r < 3; r++) {
            int item = t + 288*r;
            if (item < 800) {
                int q = item >> 5, c_l = item & 31;
                float a = 0.f;
                #pragma unroll
                for (int xx = 0; xx < HW; xx++) a += tile[c_l*37 + xx]*wv2s[q*HW + xx];
                g_v2[(size_t)(pb + q)*CCH + c0 + c_l] = a;
            }
        }
        __syncthreads();
    }
}

// fused v1 + s2 + attsel; per bq, smem-tiled Q pass
__global__ void __launch_bounds__(288) k_v1s2(const float* __restrict__ Q,
                                              const float* __restrict__ qt) {
    int bq = blockIdx.x; int b = bq/NQ, q = bq%NQ;
    int t = threadIdx.x;
    __shared__ float v2s[WAY*CCH];
    __shared__ float wv1s[WAY][HW];
    __shared__ float tile[32*37];
    __shared__ float rn2s[HW];
    __shared__ float s2s[WAY][HW];
    __shared__ float mx[WAY], sm[WAY], qts[WAY];
    {
        float4* dst = (float4*)v2s;
        for (int i4 = t; i4 < WAY*CCH/4; i4 += 288) {
            int i = i4/(CCH/4);
            const float4* src = (const float4*)(g_v2 + (size_t)((b*WAY + i)*NQ + q)*CCH);
            dst[i4] = src[i4 - i*(CCH/4)];
        }
    }
    if (t < WAY*HW) wv1s[t/HW][t%HW] = g_wv1[((b*WAY + t/HW)*NQ + q)*HW + t%HW];
    if (t < HW) rn2s[t] = g_rn2[bq*HW + t];
    if (t < WAY) qts[t] = qt[(size_t)bq*WAY + t];
    __syncthreads();
    const float* Qb = Q + (size_t)bq*CHW;
    int x = t%36, trow = t/36;
    int si = (t < 180) ? t/36 : 0;
    int sx = t%36;
    float s2a = 0.f;
    for (int c0 = 0; c0 < CCH; c0 += 32) {
        #pragma unroll
        for (int j = 0; j < 4; j++)
            tile[(trow + 8*j)*37 + x] = Qb[(c0 + trow + 8*j)*HW + x];
        __syncthreads();
        if (t < 160) {
            int i = t >> 5, c_l = t & 31;
            float a = 0.f;
            #pragma unroll
            for (int y = 0; y < HW; y++) a += tile[c_l*37 + y]*wv1s[i][y];
            g_v1[(size_t)((b*WAY + i)*NQ + q)*CCH + c0 + c_l] = a;
        }
        if (t < 180) {
            #pragma unroll
            for (int c = 0; c < 32; c++) s2a += v2s[si*CCH + c0 + c]*tile[c*37 + sx];
        }
        __syncthreads();
    }
    if (t < 180) s2s[si][sx] = s2a * rn2s[sx] * (1.f/36.f);
    __syncthreads();
    if (t < WAY) {
        float m = -1e30f;
        #pragma unroll
        for (int yy = 0; yy < HW; yy++) m = fmaxf(m, s2s[t][yy]);
        mx[t] = m;
    }
    __syncthreads();
    if (t < 180) s2s[si][sx] = expf((s2s[si][sx] - mx[si])*40.f);
    __syncthreads();
    if (t < WAY) {
        float s = 0.f;
        #pragma unroll
        for (int yy = 0; yy < HW; yy++) s += s2s[t][yy];
        sm[t] = s;
    }
    __syncthreads();
    if (t < HW) {
        float a = 0.f;
        #pragma unroll
        for (int i = 0; i < WAY; i++) a += (s2s[i][t]/sm[i] + 1.f)*qts[i];
        g_asel[bq*HW + t] = a;
    }
}

// fused s1 + softmax + proto-pool + l2 prep; per (b,i, q-chunk16)
__global__ void __launch_bounds__(288) k_s1pool() {
    int bi = blockIdx.x; int qc = blockIdx.y*16;
    const float* P = g_protos + (size_t)bi*CHW;
    __shared__ float v1s[16*CCH];     // 32KB
    __shared__ float att[16][HW];
    __shared__ float rn1s[HW];
    __shared__ float mx[16], sm[16];
    __shared__ float wred[9][16];
    int t = threadIdx.x;
    if (t < HW) rn1s[t] = g_rn1[bi*HW + t];
    {
        float4* dst = (float4*)v1s;
        const float4* src = (const float4*)g_v1;
        for (int i4 = t; i4 < 16*CCH/4; i4 += 288) {
            int ql = i4/(CCH/4);
            int qq = qc + ql;
            dst[i4] = (qq < NQ) ? src[(size_t)(bi*NQ + qq)*(CCH/4) + (i4 - ql*(CCH/4))]
                                : make_float4(0.f,0.f,0.f,0.f);
        }
    }
    __syncthreads();
    int qg = t/36, x = t%36;
    float a0 = 0.f, a1 = 0.f;
    for (int cc = 0; cc < CCH; cc++) {
        float pv = P[cc*HW + x];
        a0 += v1s[qg*CCH + cc]*pv;
        a1 += v1s[(qg+8)*CCH + cc]*pv;
    }
    att[qg][x]   = a0*rn1s[x]*(1.f/36.f);
    att[qg+8][x] = a1*rn1s[x]*(1.f/36.f);
    __syncthreads();
    if (t < 16) {
        float m = -1e30f;
        #pragma unroll
        for (int xx = 0; xx < HW; xx++) m = fmaxf(m, att[t][xx]);
        mx[t] = m;
    }
    __syncthreads();
    att[qg][x]   = expf((att[qg][x]   - mx[qg])*40.f);
    att[qg+8][x] = expf((att[qg+8][x] - mx[qg+8])*40.f);
    __syncthreads();
    if (t < 16) {
        float s = 0.f;
        #pragma unroll
        for (int xx = 0; xx < HW; xx++) s += att[t][xx];
        sm[t] = s;
    }
    __syncthreads();
    att[qg][x]   = att[qg][x]/sm[qg]     + 1.f;
    att[qg+8][x] = att[qg+8][x]/sm[qg+8] + 1.f;
    __syncthreads();
    // pool: pooled[q,c] = (1/36) sum_x P[c,x]*att[q][x]; overwrite g_v1
    float ssq[16];
    #pragma unroll
    for (int k = 0; k < 16; k++) ssq[k] = 0.f;
    for (int c = t; c < CCH; c += 288) {
        const float4* row4 = (const float4*)(P + c*HW);
        float row[HW];
        #pragma unroll
        for (int y4 = 0; y4 < 9; y4++) {
            float4 v = row4[y4];
            row[y4*4] = v.x; row[y4*4+1] = v.y; row[y4*4+2] = v.z; row[y4*4+3] = v.w;
        }
        #pragma unroll
        for (int k = 0; k < 16; k++) {
            float a = 0.f;
            #pragma unroll
            for (int xx = 0; xx < HW; xx++) a += row[xx]*att[k][xx];
            a *= (1.f/36.f);
            int qq = qc + k;
            if (qq < NQ) g_v1[(size_t)(bi*NQ + qq)*CCH + c] = a;
            ssq[k] += a*a;
        }
    }
    #pragma unroll
    for (int off = 16; off > 0; off >>= 1)
        #pragma unroll
        for (int k = 0; k < 16; k++) ssq[k] += __shfl_xor_sync(0xffffffffu, ssq[k], off);
    int warp = t >> 5, lane = t & 31;
    if (lane == 0)
        #pragma unroll
        for (int k = 0; k < 16; k++) wred[warp][k] = ssq[k];
    __syncthreads();
    if (t < 16) {
        float s = 0.f;
        #pragma unroll
        for (int w = 0; w < 9; w++) s += wred[w][t];
        int qq = qc + t;
        if (qq < NQ) g_pnf[bi*NQ + qq] = 1.f/fmaxf(sqrtf(s), 1e-12f);
    }
}

// cls_scores; per bq streaming Q (float4)
__global__ void __launch_bounds__(288) k_cls(const float* __restrict__ Q,
                                             float* __restrict__ out2) {
    int bq = blockIdx.x; int b = bq/NQ, q = bq%NQ;
    int t = threadIdx.x;
    __shared__ float pn[WAY*CCH];
    __shared__ float redA[20][288];
    __shared__ float rn2s[HW];
    __shared__ float pnfs[WAY];
    {
        float4* dst = (float4*)pn;
        for (int i4 = t; i4 < WAY*CCH/4; i4 += 288) {
            int i = i4/(CCH/4);
            const float4* src = (const float4*)(g_v1 + (size_t)((b*WAY + i)*NQ + q)*CCH);
            dst[i4] = src[i4 - i*(CCH/4)];
        }
    }
    if (t < WAY) pnfs[t] = g_pnf[(b*WAY + t)*NQ + q];
    if (t < HW) rn2s[t] = g_rn2[bq*HW + t];
    __syncthreads();
    const float4* Q4 = (const float4*)(Q + (size_t)bq*CHW);
    float aacc[WAY][4];
    #pragma unroll
    for (int i = 0; i < WAY; i++)
        #pragma unroll
        for (int j = 0; j < 4; j++) aacc[i][j] = 0.f;
    #pragma unroll 2
    for (int k = 0; k < 16; k++) {
        int idx = t + 288*k;
        int c = idx/9;
        float4 v = Q4[idx];
        #pragma unroll
        for (int i = 0; i < WAY; i++) {
            float w = pn[i*CCH + c];
            aacc[i][0] += w*v.x; aacc[i][1] += w*v.y; aacc[i][2] += w*v.z; aacc[i][3] += w*v.w;
        }
    }
    #pragma unroll
    for (int i = 0; i < WAY; i++)
        #pragma unroll
        for (int j = 0; j < 4; j++) redA[i*4 + j][t] = aacc[i][j];
    __syncthreads();
    if (t < WAY*HW) {
        int i = t/HW, x = t%HW;
        int y4 = x >> 2, j = x & 3;
        float s = 0.f;
        #pragma unroll
        for (int m = 0; m < 32; m++) s += redA[i*4 + j][y4 + 9*m];
        out2[((size_t)bq*WAY + i)*HW + x] = 7.f*rn2s[x]*pnfs[i]*s;
    }
}

// logits GEMM: C[64 x 21600] = cls_w * Qall, epilogue *asel + cb
__global__ void __launch_bounds__(128) k_logit(const float* __restrict__ Q,
                                               const float* __restrict__ cw,
                                               const float* __restrict__ cb,
                                               float* __restrict__ out1) {
    int n0 = blockIdx.x*64;
    int t = threadIdx.x;
    int tn = t & 15, tm = t >> 4;
    __shared__ float As[16][72];
    __shared__ float Bs[16][68];
    int nn_l = t & 63, kgrp = t >> 6;
    int nglob = n0 + nn_l;
    bool nval = nglob < NTOT;
    int bq_l = nval ? nglob/36 : 0;
    int x_l  = nval ? nglob%36 : 0;
    const float* qbase = Q + (size_t)bq_l*CHW + x_l;
    int o_a = t >> 1, ka = (t & 1)*8;
    float acc[8][4];
    #pragma unroll
    for (int r = 0; r < 8; r++)
        #pragma unroll
        for (int j = 0; j < 4; j++) acc[r][j] = 0.f;
    for (int k0 = 0; k0 < CCH; k0 += 16) {
        float4 av0 = *(const float4*)(cw + o_a*CCH + k0 + ka);
        float4 av1 = *(const float4*)(cw + o_a*CCH + k0 + ka + 4);
        As[ka+0][o_a] = av0.x; As[ka+1][o_a] = av0.y;
        As[ka+2][o_a] = av0.z; As[ka+3][o_a] = av0.w;
        As[ka+4][o_a] = av1.x; As[ka+5][o_a] = av1.y;
        As[ka+6][o_a] = av1.z; As[ka+7][o_a] = av1.w;
        #pragma unroll
        for (int j = 0; j < 8; j++) {
            int kk = kgrp*8 + j;
            Bs[kk][nn_l] = nval ? qbase[(size_t)(k0 + kk)*HW] : 0.f;
        }
        __syncthreads();
        #pragma unroll
        for (int k = 0; k < 16; k++) {
            float4 af0 = *(const float4*)&As[k][tm*8];
            float4 af1 = *(const float4*)&As[k][tm*8 + 4];
            float4 bf  = *(const float4*)&Bs[k][tn*4];
            float am[8] = {af0.x,af0.y,af0.z,af0.w,af1.x,af1.y,af1.z,af1.w};
            float bn[4] = {bf.x,bf.y,bf.z,bf.w};
            #pragma unroll
            for (int r = 0; r < 8; r++)
                #pragma unroll
                for (int j = 0; j < 4; j++) acc[r][j] += am[r]*bn[j];
        }
        __syncthreads();
    }
    #pragma unroll
    for (int j = 0; j < 4; j++) {
        int n = n0 + tn*4 + j;
        if (n >= NTOT) continue;
        int bq = n/36, x = n%36;
        float av = g_asel[n];
        #pragma unroll
        for (int r = 0; r < 8; r++) {
            int o = tm*8 + r;
            out1[((size_t)bq*NCLS + o)*HW + x] = acc[r][j]*av + cb[o];
        }
    }
}

// ---------------- launch ----------------
extern "C" void kernel_launch(void* const* d_in, const int* in_sizes, int n_in,
                              void* d_out, int out_size) {
    (void)in_sizes; (void)n_in; (void)out_size;
    const float* support = (const float*)d_in[0];
    const float* query   = (const float*)d_in[1];
    const float* st      = (const float*)d_in[2];
    const float* qt      = (const float*)d_in[3];
    const float* w1      = (const float*)d_in[4];
    const float* b1      = (const float*)d_in[5];
    const float* gam     = (const float*)d_in[6];
    const float* bet     = (const float*)d_in[7];
    const float* w2      = (const float*)d_in[8];
    const float* b2      = (const float*)d_in[9];
    const float* cw      = (const float*)d_in[10];
    const float* cb      = (const float*)d_in[11];
    float* out1 = (float*)d_out;                               // logits 600*64*36
    float* out2 = out1 + (size_t)BB*NQ*NCLS*HW;                // cls_scores 600*5*36

    k_protos   <<<dim3(16, BB), 288>>>(support, st);
    k_prep1    <<<BB*WAY, 288>>>();
    k_prep2ch1 <<<BB*NQ, 288>>>(query, w1, b1);
    k_ch2      <<<dim3(BB*WAY, 5), 288>>>(w1, b1);
    k_aw       <<<PAIRS/4, 288>>>(gam, bet, w2, b2);
    k_v2       <<<dim3(BB*WAY, 3), 288>>>();
    k_v1s2     <<<BB*NQ, 288>>>(query, qt);
    k_s1pool   <<<dim3(BB*WAY, 5), 288>>>();
    k_cls      <<<BB*NQ, 288>>>(query, out2);
    k_logit    <<<(NTOT + 63)/64, 128>>>(query, cw, cb, out1);
}

// round 4
// speedup vs baseline: 2.3380x; 1.0261x over previous
#include <cuda_runtime.h>
#include <math.h>

#define BB   8
#define NS   25
#define NQ   75
#define WAY  5
#define CCH  512
#define HW   36
#define MID  6
#define NCLS 64
#define PAIRS (BB*WAY*NQ)   /* 3000 */
#define CHW  (CCH*HW)       /* 18432 */
#define CHW4 (CHW/4)        /* 4608 */
#define NTOT (BB*NQ*HW)     /* 21600 */

// ---------------- scratch ----------------
__device__ float g_protos[BB*WAY*CHW];     // [b,i,c,x]
__device__ float g_rn1 [BB*WAY*HW];
__device__ float g_mw1 [BB*WAY*CCH];
__device__ float g_rn2 [BB*NQ*HW];
__device__ float g_mw2 [BB*NQ*CCH];
__device__ float g_yv  [2*PAIRS*MID];
__device__ float g_stats[24];
__device__ float g_wv1 [PAIRS*HW];
__device__ float g_wv2 [PAIRS*HW];
__device__ float g_v1  [PAIRS*CCH];        // v1, later overwritten with NORMALIZED pooled
__device__ float g_v2  [PAIRS*CCH];
__device__ float g_asel[BB*NQ*HW];

// prototypes (float4) + zero stats
__global__ void __launch_bounds__(288) k_protos(const float* __restrict__ sup,
                                                const float* __restrict__ st) {
    int b = blockIdx.y, t = threadIdx.x;
    if (blockIdx.x == 0 && b == 0 && t < 24) g_stats[t] = 0.f;
    __shared__ float sts[NS*WAY];
    __shared__ float rcnt[WAY];
    if (t < NS*WAY) sts[t] = st[b*NS*WAY + t];
    __syncthreads();
    if (t < WAY) { float s = 0.f; for (int n = 0; n < NS; n++) s += sts[n*WAY + t]; rcnt[t] = 1.f/s; }
    __syncthreads();
    int d4 = blockIdx.x*288 + t;           // grid.x = 16, 16*288 = 4608
    const float4* sb = (const float4*)sup + (size_t)b*NS*CHW4 + d4;
    float4 acc[WAY];
    #pragma unroll
    for (int w = 0; w < WAY; w++) acc[w] = make_float4(0.f,0.f,0.f,0.f);
    for (int n = 0; n < NS; n++) {
        float4 v = sb[(size_t)n*CHW4];
        #pragma unroll
        for (int w = 0; w < WAY; w++) {
            float s = sts[n*WAY + w];
            acc[w].x += s*v.x; acc[w].y += s*v.y; acc[w].z += s*v.z; acc[w].w += s*v.w;
        }
    }
    #pragma unroll
    for (int w = 0; w < WAY; w++) {
        float r = rcnt[w];
        float4 o = make_float4(acc[w].x*r, acc[w].y*r, acc[w].z*r, acc[w].w*r);
        ((float4*)g_protos)[(size_t)(b*WAY + w)*CHW4 + d4] = o;
    }
}

// per (b,i): rn1, mw1
__global__ void __launch_bounds__(288) k_prep1() {
    int bi = blockIdx.x, t = threadIdx.x;
    const float4* P4 = (const float4*)(g_protos + (size_t)bi*CHW);
    __shared__ float part[288*4];
    __shared__ float rn1s[HW];
    float s0=0.f,s1=0.f,s2=0.f,s3=0.f;
    #pragma unroll 4
    for (int k = 0; k < 16; k++) {
        float4 v = P4[t + 288*k];
        s0 += v.x*v.x; s1 += v.y*v.y; s2 += v.z*v.z; s3 += v.w*v.w;
    }
    part[4*t]=s0; part[4*t+1]=s1; part[4*t+2]=s2; part[4*t+3]=s3;
    __syncthreads();
    if (t < HW) {
        int y4 = t >> 2, j = t & 3;
        float s = 0.f;
        #pragma unroll
        for (int m = 0; m < 32; m++) s += part[4*(y4 + 9*m) + j];
        float r = 1.f/fmaxf(sqrtf(s), 1e-12f);
        rn1s[t] = r; g_rn1[bi*HW + t] = r;
    }
    __syncthreads();
    for (int c = t; c < CCH; c += 288) {
        const float4* row = P4 + c*9;
        float a = 0.f;
        #pragma unroll
        for (int y4 = 0; y4 < 9; y4++) {
            float4 v = row[y4];
            a += v.x*rn1s[y4*4] + v.y*rn1s[y4*4+1] + v.z*rn1s[y4*4+2] + v.w*rn1s[y4*4+3];
        }
        g_mw1[bi*CCH + c] = a*(1.f/36.f);
    }
}

// fused prep2 + ch1: per bq, one DRAM pass over Q (+L1 re-pass for mw2)
__global__ void __launch_bounds__(288) k_prep2ch1(const float* __restrict__ Q,
                                                  const float* __restrict__ w1,
                                                  const float* __restrict__ b1) {
    int bq = blockIdx.x; int b = bq/NQ, q = bq%NQ;
    int t = threadIdx.x;
    __shared__ float mw1s[WAY*CCH];
    __shared__ float redA[20][288];
    __shared__ float part[288*4];
    __shared__ float rn2s[HW];
    __shared__ float ch1s[WAY][HW];
    {
        const float4* src = (const float4*)(g_mw1 + b*WAY*CCH);
        float4* dst = (float4*)mw1s;
        for (int i4 = t; i4 < WAY*CCH/4; i4 += 288) dst[i4] = src[i4];
    }
    __syncthreads();
    const float4* Q4 = (const float4*)(Q + (size_t)bq*CHW);
    float aacc[WAY][4];
    float sq[4] = {0.f,0.f,0.f,0.f};
    #pragma unroll
    for (int i = 0; i < WAY; i++)
        #pragma unroll
        for (int j = 0; j < 4; j++) aacc[i][j] = 0.f;
    #pragma unroll 4
    for (int k = 0; k < 16; k++) {
        int idx = t + 288*k;
        int c = idx/9;
        float4 v = Q4[idx];
        sq[0] += v.x*v.x; sq[1] += v.y*v.y; sq[2] += v.z*v.z; sq[3] += v.w*v.w;
        #pragma unroll
        for (int i = 0; i < WAY; i++) {
            float w = mw1s[i*CCH + c];
            aacc[i][0] += w*v.x; aacc[i][1] += w*v.y; aacc[i][2] += w*v.z; aacc[i][3] += w*v.w;
        }
    }
    #pragma unroll
    for (int j = 0; j < 4; j++) part[4*t + j] = sq[j];
    #pragma unroll
    for (int i = 0; i < WAY; i++)
        #pragma unroll
        for (int j = 0; j < 4; j++) redA[i*4 + j][t] = aacc[i][j];
    __syncthreads();
    if (t < HW) {
        int y4 = t >> 2, j = t & 3;
        float s = 0.f;
        #pragma unroll
        for (int m = 0; m < 32; m++) s += part[4*(y4 + 9*m) + j];
        float r = 1.f/fmaxf(sqrtf(s), 1e-12f);
        rn2s[t] = r; g_rn2[bq*HW + t] = r;
    }
    __syncthreads();
    if (t < WAY*HW) {
        int i = t/HW, y = t%HW;
        int y4 = y >> 2, j = y & 3;
        float s = 0.f;
        #pragma unroll
        for (int m = 0; m < 32; m++) s += redA[i*4 + j][y4 + 9*m];
        ch1s[i][y] = s*rn2s[y];
    }
    // pass2: mw2 (Q rows L1-resident)
    for (int c = t; c < CCH; c += 288) {
        const float4* row = Q4 + c*9;
        float a = 0.f;
        #pragma unroll
        for (int y4 = 0; y4 < 9; y4++) {
            float4 v = row[y4];
            a += v.x*rn2s[y4*4] + v.y*rn2s[y4*4+1] + v.z*rn2s[y4*4+2] + v.w*rn2s[y4*4+3];
        }
        g_mw2[bq*CCH + c] = a*(1.f/36.f);
    }
    __syncthreads();
    if (t < WAY*MID) {
        int i = t/MID, m = t%MID;
        float a = b1[m];
        #pragma unroll
        for (int y = 0; y < HW; y++) a += w1[m*HW + y]*ch1s[i][y];
        int p = (b*WAY + i)*NQ + q;
        g_yv[p*MID + m] = a;
        atomicAdd(&g_stats[m], a); atomicAdd(&g_stats[MID + m], a*a);
    }
}

// path2 conv input + conv1 + BN stats; per (b,i, q-chunk16); smem-tiled P
__global__ void __launch_bounds__(288) k_ch2(const float* __restrict__ w1,
                                             const float* __restrict__ b1) {
    int bi = blockIdx.x; int qc = blockIdx.y*16;
    int b = bi/WAY;
    const float* P = g_protos + (size_t)bi*CHW;
    __shared__ float mw2s[16*CCH];
    __shared__ float tile[32*37];
    __shared__ float ch2s[16][HW];
    __shared__ float rn1s[HW];
    int t = threadIdx.x;
    if (t < HW) rn1s[t] = g_rn1[bi*HW + t];
    {
        float4* dst = (float4*)mw2s;
        const float4* src = (const float4*)g_mw2;
        for (int i4 = t; i4 < 16*CCH/4; i4 += 288) {
            int ql = i4 >> 7; int qq = qc + ql;
            dst[i4] = (qq < NQ) ? src[(size_t)(b*NQ + qq)*(CCH/4) + (i4 & 127)]
                                : make_float4(0.f,0.f,0.f,0.f);
        }
    }
    __syncthreads();
    int x = t%36, trow = t/36;     // trow 0..7
    float acc0 = 0.f, acc1 = 0.f;
    for (int c0 = 0; c0 < CCH; c0 += 32) {
        #pragma unroll
        for (int j = 0; j < 4; j++)
            tile[(trow + 8*j)*37 + x] = P[(c0 + trow + 8*j)*HW + x];
        __syncthreads();
        #pragma unroll
        for (int c = 0; c < 32; c++) {
            float pv = tile[c*37 + x];
            acc0 += mw2s[trow*CCH + c0 + c]*pv;
            acc1 += mw2s[(trow+8)*CCH + c0 + c]*pv;
        }
        __syncthreads();
    }
    ch2s[trow][x]   = acc0*rn1s[x];
    ch2s[trow+8][x] = acc1*rn1s[x];
    __syncthreads();
    if (t < 16*MID) {
        int g2 = t/MID, m = t%MID; int q2 = qc + g2;
        if (q2 < NQ) {
            float s = b1[m];
            #pragma unroll
            for (int xx = 0; xx < HW; xx++) s += w1[m*HW + xx]*ch2s[g2][xx];
            int p = bi*NQ + q2;
            g_yv[PAIRS*MID + p*MID + m] = s;
            atomicAdd(&g_stats[2*MID + m], s); atomicAdd(&g_stats[3*MID + m], s*s);
        }
    }
}

// BN finalize (local) + BN+relu+conv2 -> wv1, wv2; 4 pairs per block
__global__ void __launch_bounds__(288) k_aw(const float* __restrict__ gam,
                                            const float* __restrict__ bet,
                                            const float* __restrict__ w2,
                                            const float* __restrict__ b2) {
    __shared__ float h[4][12];
    __shared__ float bnps[24];
    int t = threadIdx.x;
    if (t < 12) {
        int path = t/MID, m = t%MID;
        float sum = g_stats[path*12 + m];
        float sqs = g_stats[path*12 + MID + m];
        float mu  = sum/(float)PAIRS;
        float var = sqs/(float)PAIRS - mu*mu;
        bnps[path*12 + m]       = mu;
        bnps[path*12 + MID + m] = rsqrtf(var + 1e-5f);
    }
    __syncthreads();
    int sub = t/72, tt = t%72;
    int p = blockIdx.x*4 + sub;
    int b = p/(WAY*NQ); int rem = p%(WAY*NQ); int i = rem/NQ; int q = rem%NQ;
    int bq = b*NQ + q;
    if (tt < 12) {
        int path = tt/MID, m = tt%MID;
        float v   = g_yv[path*PAIRS*MID + p*MID + m];
        float mu  = bnps[path*12 + m];
        float ist = bnps[path*12 + MID + m];
        float z = gam[m]*(v - mu)*ist + bet[m];
        h[sub][tt] = fmaxf(z, 0.f);
    }
    __syncthreads();
    int path = tt/HW, k = tt%HW;
    float a = b2[k];
    #pragma unroll
    for (int m = 0; m < MID; m++) a += w2[k*MID + m]*h[sub][path*MID + m];
    if (path == 0) g_wv1[p*HW + k] = a * g_rn2[bq*HW + k];
    else           g_wv2[p*HW + k] = a * g_rn1[(b*WAY + i)*HW + k];
}

// v2[p,c] = sum_x P[c,x]*wv2[p,x]; per (b,i, q-chunk25); smem-tiled
__global__ void __launch_bounds__(288) k_v2() {
    int bi = blockIdx.x; int qc = blockIdx.y*25;
    int pb = bi*NQ + qc;
    const float* P = g_protos + (size_t)bi*CHW;
    __shared__ float wv2s[25*HW];
    __shared__ float tile[32*37];
    int t = threadIdx.x;
    for (int idx = t; idx < 25*HW; idx += 288) wv2s[idx] = g_wv2[pb*HW + idx];
    __syncthreads();
    int x = t%36, trow = t/36;
    for (int c0 = 0; c0 < CCH; c0 += 32) {
        #pragma unroll
        for (int j = 0; j < 4; j++)
            tile[(trow + 8*j)*37 + x] = P[(c0 + trow + 8*j)*HW + x];
        __syncthreads();
        #pragma unroll
        for (int r = 0; r < 3; r++) {
            int item = t + 288*r;
            if (item < 800) {
                int q = item >> 5, c_l = item & 31;
                float a = 0.f;
                #pragma unroll
                for (int xx = 0; xx < HW; xx++) a += tile[c_l*37 + xx]*wv2s[q*HW + xx];
                g_v2[(size_t)(pb + q)*CCH + c0 + c_l] = a;
            }
        }
        __syncthreads();
    }
}

// fused v1 + s2 + attsel; per bq, smem-tiled Q pass
__global__ void __launch_bounds__(288) k_v1s2(const float* __restrict__ Q,
                                              const float* __restrict__ qt) {
    int bq = blockIdx.x; int b = bq/NQ, q = bq%NQ;
    int t = threadIdx.x;
    __shared__ float v2s[WAY*CCH];
    __shared__ float wv1s[WAY][HW];
    __shared__ float tile[32*37];
    __shared__ float rn2s[HW];
    __shared__ float s2s[WAY][HW];
    __shared__ float mx[WAY], sm[WAY], qts[WAY];
    {
        float4* dst = (float4*)v2s;
        for (int i4 = t; i4 < WAY*CCH/4; i4 += 288) {
            int i = i4/(CCH/4);
            const float4* src = (const float4*)(g_v2 + (size_t)((b*WAY + i)*NQ + q)*CCH);
            dst[i4] = src[i4 - i*(CCH/4)];
        }
    }
    if (t < WAY*HW) wv1s[t/HW][t%HW] = g_wv1[((b*WAY + t/HW)*NQ + q)*HW + t%HW];
    if (t < HW) rn2s[t] = g_rn2[bq*HW + t];
    if (t < WAY) qts[t] = qt[(size_t)bq*WAY + t];
    __syncthreads();
    const float* Qb = Q + (size_t)bq*CHW;
    int x = t%36, trow = t/36;
    int si = (t < 180) ? t/36 : 0;
    int sx = t%36;
    float s2a = 0.f;
    for (int c0 = 0; c0 < CCH; c0 += 32) {
        #pragma unroll
        for (int j = 0; j < 4; j++)
            tile[(trow + 8*j)*37 + x] = Qb[(c0 + trow + 8*j)*HW + x];
        __syncthreads();
        if (t < 160) {
            int i = t >> 5, c_l = t & 31;
            float a = 0.f;
            #pragma unroll
            for (int y = 0; y < HW; y++) a += tile[c_l*37 + y]*wv1s[i][y];
            g_v1[(size_t)((b*WAY + i)*NQ + q)*CCH + c0 + c_l] = a;
        }
        if (t < 180) {
            #pragma unroll
            for (int c = 0; c < 32; c++) s2a += v2s[si*CCH + c0 + c]*tile[c*37 + sx];
        }
        __syncthreads();
    }
    if (t < 180) s2s[si][sx] = s2a * rn2s[sx] * (1.f/36.f);
    __syncthreads();
    if (t < WAY) {
        float m = -1e30f;
        #pragma unroll
        for (int yy = 0; yy < HW; yy++) m = fmaxf(m, s2s[t][yy]);
        mx[t] = m;
    }
    __syncthreads();
    if (t < 180) s2s[si][sx] = expf((s2s[si][sx] - mx[si])*40.f);
    __syncthreads();
    if (t < WAY) {
        float s = 0.f;
        #pragma unroll
        for (int yy = 0; yy < HW; yy++) s += s2s[t][yy];
        sm[t] = s;
    }
    __syncthreads();
    if (t < HW) {
        float a = 0.f;
        #pragma unroll
        for (int i = 0; i < WAY; i++) a += (s2s[i][t]/sm[i] + 1.f)*qts[i];
        g_asel[bq*HW + t] = a;
    }
}

// fused s1 + softmax + proto-pool + l2norm; per (b,i, q-chunk16); smem-tiled P
// overwrites g_v1 with NORMALIZED pooled protos
__global__ void __launch_bounds__(288) k_s1pool() {
    int bi = blockIdx.x; int qc = blockIdx.y*16;
    const float* P = g_protos + (size_t)bi*CHW;
    __shared__ float v1s[16*CCH];     // 32KB: phase A = v1 weights; phase C = pooled
    __shared__ float tile[32*37];
    __shared__ float att[16][HW];
    __shared__ float rn1s[HW];
    __shared__ float mx[16], sm[16];
    __shared__ float pnfs[16];
    int t = threadIdx.x;
    if (t < HW) rn1s[t] = g_rn1[bi*HW + t];
    {
        float4* dst = (float4*)v1s;
        const float4* src = (const float4*)g_v1;
        for (int i4 = t; i4 < 16*CCH/4; i4 += 288) {
            int ql = i4 >> 7;
            int qq = qc + ql;
            dst[i4] = (qq < NQ) ? src[(size_t)(bi*NQ + qq)*(CCH/4) + (i4 & 127)]
                                : make_float4(0.f,0.f,0.f,0.f);
        }
    }
    __syncthreads();
    int x = t%36, trow = t/36;     // trow 0..7
    // phase A: att_pre[q,x] = sum_c v1[q,c]*P[c,x]
    float acc0 = 0.f, acc1 = 0.f;
    for (int c0 = 0; c0 < CCH; c0 += 32) {
        #pragma unroll
        for (int j = 0; j < 4; j++)
            tile[(trow + 8*j)*37 + x] = P[(c0 + trow + 8*j)*HW + x];
        __syncthreads();
        #pragma unroll
        for (int c = 0; c < 32; c++) {
            float pv = tile[c*37 + x];
            acc0 += v1s[trow*CCH + c0 + c]*pv;
            acc1 += v1s[(trow+8)*CCH + c0 + c]*pv;
        }
        __syncthreads();
    }
    att[trow][x]   = acc0*rn1s[x]*(1.f/36.f);
    att[trow+8][x] = acc1*rn1s[x]*(1.f/36.f);
    __syncthreads();
    if (t < 16) {
        float m = -1e30f;
        #pragma unroll
        for (int xx = 0; xx < HW; xx++) m = fmaxf(m, att[t][xx]);
        mx[t] = m;
    }
    __syncthreads();
    att[trow][x]   = expf((att[trow][x]   - mx[trow])*40.f);
    att[trow+8][x] = expf((att[trow+8][x] - mx[trow+8])*40.f);
    __syncthreads();
    if (t < 16) {
        float s = 0.f;
        #pragma unroll
        for (int xx = 0; xx < HW; xx++) s += att[t][xx];
        sm[t] = s;
    }
    __syncthreads();
    att[trow][x]   = att[trow][x]/sm[trow]     + 1.f;
    att[trow+8][x] = att[trow+8][x]/sm[trow+8] + 1.f;
    __syncthreads();
    // phase C: pooled[q,c] = (1/36) sum_x P[c,x]*att[q,x] into v1s; ssq per q
    int q_a = t >> 5, c_l = t & 31;    // warp == q_a (0..8)
    int q_b = q_a + 9;                 // valid when q_b < 16  (t < 224)
    float ssq_a = 0.f, ssq_b = 0.f;
    for (int c0 = 0; c0 < CCH; c0 += 32) {
        #pragma unroll
        for (int j = 0; j < 4; j++)
            tile[(trow + 8*j)*37 + x] = P[(c0 + trow + 8*j)*HW + x];
        __syncthreads();
        {
            float a = 0.f;
            #pragma unroll
            for (int xx = 0; xx < HW; xx++) a += tile[c_l*37 + xx]*att[q_a][xx];
            a *= (1.f/36.f);
            v1s[q_a*CCH + c0 + c_l] = a;
            ssq_a += a*a;
        }
        if (q_b < 16) {
            float a = 0.f;
            #pragma unroll
            for (int xx = 0; xx < HW; xx++) a += tile[c_l*37 + xx]*att[q_b][xx];
            a *= (1.f/36.f);
            v1s[q_b*CCH + c0 + c_l] = a;
            ssq_b += a*a;
        }
        __syncthreads();
    }
    #pragma unroll
    for (int off = 16; off > 0; off >>= 1) {
        ssq_a += __shfl_xor_sync(0xffffffffu, ssq_a, off);
        ssq_b += __shfl_xor_sync(0xffffffffu, ssq_b, off);
    }
    int lane = t & 31, warp = t >> 5;
    if (lane == 0) {
        pnfs[warp] = 1.f/fmaxf(sqrtf(ssq_a), 1e-12f);
        if (warp < 7) pnfs[warp + 9] = 1.f/fmaxf(sqrtf(ssq_b), 1e-12f);
    }
    __syncthreads();
    // write normalized pooled
    for (int idx = t; idx < 16*CCH; idx += 288) {
        int ql = idx >> 9; int qq = qc + ql;
        if (qq < NQ) g_v1[(size_t)(bi*NQ + qq)*CCH + (idx & 511)] = v1s[idx]*pnfs[ql];
    }
}

// logits GEMM + fused cls_scores.
// C[64 x 21600] = cls_w * Qall, epilogue *asel + cb  (out1)
// out2[bq,i,x] = 7*rn2[n]*sum_c poolednorm[bq,i,c]*Q[c,n]
__global__ void __launch_bounds__(128) k_logit(const float* __restrict__ Q,
                                               const float* __restrict__ cw,
                                               const float* __restrict__ cb,
                                               float* __restrict__ out1,
                                               float* __restrict__ out2) {
    int n0 = blockIdx.x*64;
    int t = threadIdx.x;
    int tn = t & 15, tm = t >> 4;
    __shared__ float shAB[2240];        // As[16][72] @0 ; Bs[16][68] @1152 ; red[1280] reuse
    __shared__ float pools[3*WAY*CCH];  // 30KB normalized pooled for up to 3 bq
    int bq0 = n0/36;
    {
        float4* dst = (float4*)pools;
        const float4* src = (const float4*)g_v1;
        for (int i4 = t; i4 < 3*WAY*(CCH/4); i4 += 128) {
            int r = i4/640; int rem = i4 - r*640; int i = rem >> 7; int c4 = rem & 127;
            int bq = bq0 + r;
            float4 v = make_float4(0.f,0.f,0.f,0.f);
            if (bq < BB*NQ) {
                int b = bq/NQ, q = bq%NQ;
                v = src[(size_t)((b*WAY + i)*NQ + q)*(CCH/4) + c4];
            }
            dst[i4] = v;
        }
    }
    int nn_l = t & 63, kgrp = t >> 6;
    int nglob = n0 + nn_l;
    bool nval = nglob < NTOT;
    int bq_l = nval ? nglob/36 : 0;
    int x_l  = nval ? nglob%36 : 0;
    const float* qbase = Q + (size_t)bq_l*CHW + x_l;
    int o_a = t >> 1, ka = (t & 1)*8;
    float acc[8][4];
    float accc[4][WAY];
    #pragma unroll
    for (int r = 0; r < 8; r++)
        #pragma unroll
        for (int j = 0; j < 4; j++) acc[r][j] = 0.f;
    #pragma unroll
    for (int j = 0; j < 4; j++)
        #pragma unroll
        for (int i = 0; i < WAY; i++) accc[j][i] = 0.f;
    int rj[4];
    #pragma unroll
    for (int j = 0; j < 4; j++) {
        int n = n0 + tn*4 + j;
        rj[j] = (n < NTOT) ? (n/36 - bq0) : 0;
    }
    for (int k0 = 0; k0 < CCH; k0 += 16) {
        float4 av0 = *(const float4*)(cw + o_a*CCH + k0 + ka);
        float4 av1 = *(const float4*)(cw + o_a*CCH + k0 + ka + 4);
        shAB[(ka+0)*72 + o_a] = av0.x; shAB[(ka+1)*72 + o_a] = av0.y;
        shAB[(ka+2)*72 + o_a] = av0.z; shAB[(ka+3)*72 + o_a] = av0.w;
        shAB[(ka+4)*72 + o_a] = av1.x; shAB[(ka+5)*72 + o_a] = av1.y;
        shAB[(ka+6)*72 + o_a] = av1.z; shAB[(ka+7)*72 + o_a] = av1.w;
        #pragma unroll
        for (int j = 0; j < 8; j++) {
            int kk = kgrp*8 + j;
            shAB[1152 + kk*68 + nn_l] = nval ? qbase[(size_t)(k0 + kk)*HW] : 0.f;
        }
        __syncthreads();
        #pragma unroll
        for (int k = 0; k < 16; k++) {
            float4 af0 = *(const float4*)&shAB[k*72 + tm*8];
            float4 af1 = *(const float4*)&shAB[k*72 + tm*8 + 4];
            float4 bf  = *(const float4*)&shAB[1152 + k*68 + tn*4];
            float am[8] = {af0.x,af0.y,af0.z,af0.w,af1.x,af1.y,af1.z,af1.w};
            float bn[4] = {bf.x,bf.y,bf.z,bf.w};
            #pragma unroll
            for (int r = 0; r < 8; r++)
                #pragma unroll
                for (int j = 0; j < 4; j++) acc[r][j] += am[r]*bn[j];
        }
        // cls partial: this thread covers k = tm*2, tm*2+1
        #pragma unroll
        for (int kk2 = 0; kk2 < 2; kk2++) {
            int kk = tm*2 + kk2;
            #pragma unroll
            for (int j = 0; j < 4; j++) {
                float bn = shAB[1152 + kk*68 + tn*4 + j];
                #pragma unroll
                for (int i = 0; i < WAY; i++)
                    accc[j][i] += pools[rj[j]*WAY*CCH + i*CCH + k0 + kk]*bn;
            }
        }
        __syncthreads();
    }
    // logits epilogue
    #pragma unroll
    for (int j = 0; j < 4; j++) {
        int n = n0 + tn*4 + j;
        if (n >= NTOT) continue;
        int bq = n/36, x = n%36;
        float av = g_asel[n];
        #pragma unroll
        for (int r = 0; r < 8; r++) {
            int o = tm*8 + r;
            out1[((size_t)bq*NCLS + o)*HW + x] = acc[r][j]*av + cb[o];
        }
    }
    // cls reduce: shfl over tm-pairs, then smem over 4 groups (reuse shAB)
    #pragma unroll
    for (int j = 0; j < 4; j++)
        #pragma unroll
        for (int i = 0; i < WAY; i++)
            accc[j][i] += __shfl_xor_sync(0xffffffffu, accc[j][i], 16);
    if ((tm & 1) == 0) {
        int g = tm >> 1;
        #pragma unroll
        for (int j = 0; j < 4; j++)
            #pragma unroll
            for (int i = 0; i < WAY; i++)
                shAB[g*320 + (tn*4 + j)*WAY + i] = accc[j][i];
    }
    __syncthreads();
    for (int idx = t; idx < 320; idx += 128) {
        int n_l = idx/WAY, i = idx%WAY;
        int n = n0 + n_l;
        if (n < NTOT) {
            float s = shAB[idx] + shAB[320 + idx] + shAB[640 + idx] + shAB[960 + idx];
            int bq = n/36, x = n%36;
            out2[((size_t)bq*WAY + i)*HW + x] = 7.f * g_rn2[n] * s;
        }
    }
}

// ---------------- launch ----------------
extern "C" void kernel_launch(void* const* d_in, const int* in_sizes, int n_in,
                              void* d_out, int out_size) {
    (void)in_sizes; (void)n_in; (void)out_size;
    const float* support = (const float*)d_in[0];
    const float* query   = (const float*)d_in[1];
    const float* st      = (const float*)d_in[2];
    const float* qt      = (const float*)d_in[3];
    const float* w1      = (const float*)d_in[4];
    const float* b1      = (const float*)d_in[5];
    const float* gam     = (const float*)d_in[6];
    const float* bet     = (const float*)d_in[7];
    const float* w2      = (const float*)d_in[8];
    const float* b2      = (const float*)d_in[9];
    const float* cw      = (const float*)d_in[10];
    const float* cb      = (const float*)d_in[11];
    float* out1 = (float*)d_out;                               // logits 600*64*36
    float* out2 = out1 + (size_t)BB*NQ*NCLS*HW;                // cls_scores 600*5*36

    k_protos   <<<dim3(16, BB), 288>>>(support, st);
    k_prep1    <<<BB*WAY, 288>>>();
    k_prep2ch1 <<<BB*NQ, 288>>>(query, w1, b1);
    k_ch2      <<<dim3(BB*WAY, 5), 288>>>(w1, b1);
    k_aw       <<<PAIRS/4, 288>>>(gam, bet, w2, b2);
    k_v2       <<<dim3(BB*WAY, 3), 288>>>();
    k_v1s2     <<<BB*NQ, 288>>>(query, qt);
    k_s1pool   <<<dim3(BB*WAY, 5), 288>>>();
    k_logit    <<<(NTOT + 63)/64, 128>>>(query, cw, cb, out1, out2);
}

// round 5
// speedup vs baseline: 2.3406x; 1.0011x over previous
#include <cuda_runtime.h>
#include <math.h>

#define BB   8
#define NS   25
#define NQ   75
#define WAY  5
#define CCH  512
#define HW   36
#define MID  6
#define NCLS 64
#define PAIRS (BB*WAY*NQ)   /* 3000 */
#define CHW  (CCH*HW)       /* 18432 */
#define CHW4 (CHW/4)        /* 4608 */
#define NTOT (BB*NQ*HW)     /* 21600 */

// ---------------- scratch ----------------
__device__ float g_protos[BB*WAY*CHW];     // [b,i,c,x]
__device__ float g_rn1 [BB*WAY*HW];
__device__ float g_mw1 [BB*WAY*CCH];
__device__ float g_pw1 [BB*WAY*MID*CCH];   // Σ_x w1[m,x]·rn1[x]·P[c,x]
__device__ float g_rn2 [BB*NQ*HW];
__device__ float g_yv  [2*PAIRS*MID];
__device__ float g_stats[24];
__device__ float g_wv1 [PAIRS*HW];
__device__ float g_v1  [PAIRS*CCH];        // v1, later NORMALIZED pooled
__device__ float g_v2  [PAIRS*CCH];
__device__ float g_asel[BB*NQ*HW];

// prototypes (float4) + zero stats
__global__ void __launch_bounds__(288) k_protos(const float* __restrict__ sup,
                                                const float* __restrict__ st) {
    int b = blockIdx.y, t = threadIdx.x;
    if (blockIdx.x == 0 && b == 0 && t < 24) g_stats[t] = 0.f;
    __shared__ float sts[NS*WAY];
    __shared__ float rcnt[WAY];
    if (t < NS*WAY) sts[t] = st[b*NS*WAY + t];
    __syncthreads();
    if (t < WAY) { float s = 0.f; for (int n = 0; n < NS; n++) s += sts[n*WAY + t]; rcnt[t] = 1.f/s; }
    __syncthreads();
    int d4 = blockIdx.x*288 + t;
    const float4* sb = (const float4*)sup + (size_t)b*NS*CHW4 + d4;
    float4 acc[WAY];
    #pragma unroll
    for (int w = 0; w < WAY; w++) acc[w] = make_float4(0.f,0.f,0.f,0.f);
    for (int n = 0; n < NS; n++) {
        float4 v = sb[(size_t)n*CHW4];
        #pragma unroll
        for (int w = 0; w < WAY; w++) {
            float s = sts[n*WAY + w];
            acc[w].x += s*v.x; acc[w].y += s*v.y; acc[w].z += s*v.z; acc[w].w += s*v.w;
        }
    }
    #pragma unroll
    for (int w = 0; w < WAY; w++) {
        float r = rcnt[w];
        float4 o = make_float4(acc[w].x*r, acc[w].y*r, acc[w].z*r, acc[w].w*r);
        ((float4*)g_protos)[(size_t)(b*WAY + w)*CHW4 + d4] = o;
    }
}

// per (b,i): rn1, mw1, pw1
__global__ void __launch_bounds__(288) k_prep1(const float* __restrict__ w1) {
    int bi = blockIdx.x, t = threadIdx.x;
    const float4* P4 = (const float4*)(g_protos + (size_t)bi*CHW);
    __shared__ float part[288*4];
    __shared__ float rn1s[HW];
    __shared__ float wr[MID][HW];
    float s0=0.f,s1=0.f,s2=0.f,s3=0.f;
    #pragma unroll 4
    for (int k = 0; k < 16; k++) {
        float4 v = P4[t + 288*k];
        s0 += v.x*v.x; s1 += v.y*v.y; s2 += v.z*v.z; s3 += v.w*v.w;
    }
    part[4*t]=s0; part[4*t+1]=s1; part[4*t+2]=s2; part[4*t+3]=s3;
    __syncthreads();
    if (t < HW) {
        int y4 = t >> 2, j = t & 3;
        float s = 0.f;
        #pragma unroll
        for (int m = 0; m < 32; m++) s += part[4*(y4 + 9*m) + j];
        float r = 1.f/fmaxf(sqrtf(s), 1e-12f);
        rn1s[t] = r; g_rn1[bi*HW + t] = r;
    }
    __syncthreads();
    if (t < MID*HW) { int m = t/HW, x = t%HW; wr[m][x] = w1[m*HW + x]*rn1s[x]; }
    __syncthreads();
    for (int c = t; c < CCH; c += 288) {
        const float4* r4 = P4 + c*9;
        float row[HW];
        #pragma unroll
        for (int y4 = 0; y4 < 9; y4++) {
            float4 v = r4[y4];
            row[4*y4] = v.x; row[4*y4+1] = v.y; row[4*y4+2] = v.z; row[4*y4+3] = v.w;
        }
        float a = 0.f;
        #pragma unroll
        for (int x = 0; x < HW; x++) a += row[x]*rn1s[x];
        g_mw1[bi*CCH + c] = a*(1.f/36.f);
        #pragma unroll
        for (int m = 0; m < MID; m++) {
            float s = 0.f;
            #pragma unroll
            for (int x = 0; x < HW; x++) s += row[x]*wr[m][x];
            g_pw1[(size_t)(bi*MID + m)*CCH + c] = s;
        }
    }
}

// fused prep2 + ch1(path1 conv1) + yv2(path2 conv1 via pw1); per bq
__global__ void __launch_bounds__(288) k_prep2ch1(const float* __restrict__ Q,
                                                  const float* __restrict__ w1,
                                                  const float* __restrict__ b1) {
    int bq = blockIdx.x; int b = bq/NQ, q = bq%NQ;
    int t = threadIdx.x;
    __shared__ float mw1s[WAY*CCH];
    __shared__ float redA[20][288];
    __shared__ float part[288*4];
    __shared__ float rn2s[HW];
    __shared__ float ch1s[WAY][HW];
    __shared__ float mw2s[CCH];
    {
        const float4* src = (const float4*)(g_mw1 + b*WAY*CCH);
        float4* dst = (float4*)mw1s;
        for (int i4 = t; i4 < WAY*CCH/4; i4 += 288) dst[i4] = src[i4];
    }
    __syncthreads();
    const float4* Q4 = (const float4*)(Q + (size_t)bq*CHW);
    float aacc[WAY][4];
    float sq[4] = {0.f,0.f,0.f,0.f};
    #pragma unroll
    for (int i = 0; i < WAY; i++)
        #pragma unroll
        for (int j = 0; j < 4; j++) aacc[i][j] = 0.f;
    #pragma unroll 4
    for (int k = 0; k < 16; k++) {
        int idx = t + 288*k;
        int c = idx/9;
        float4 v = Q4[idx];
        sq[0] += v.x*v.x; sq[1] += v.y*v.y; sq[2] += v.z*v.z; sq[3] += v.w*v.w;
        #pragma unroll
        for (int i = 0; i < WAY; i++) {
            float w = mw1s[i*CCH + c];
            aacc[i][0] += w*v.x; aacc[i][1] += w*v.y; aacc[i][2] += w*v.z; aacc[i][3] += w*v.w;
        }
    }
    #pragma unroll
    for (int j = 0; j < 4; j++) part[4*t + j] = sq[j];
    #pragma unroll
    for (int i = 0; i < WAY; i++)
        #pragma unroll
        for (int j = 0; j < 4; j++) redA[i*4 + j][t] = aacc[i][j];
    __syncthreads();
    if (t < HW) {
        int y4 = t >> 2, j = t & 3;
        float s = 0.f;
        #pragma unroll
        for (int m = 0; m < 32; m++) s += part[4*(y4 + 9*m) + j];
        float r = 1.f/fmaxf(sqrtf(s), 1e-12f);
        rn2s[t] = r; g_rn2[bq*HW + t] = r;
    }
    __syncthreads();
    if (t < WAY*HW) {
        int i = t/HW, y = t%HW;
        int y4 = y >> 2, j = y & 3;
        float s = 0.f;
        #pragma unroll
        for (int m = 0; m < 32; m++) s += redA[i*4 + j][y4 + 9*m];
        ch1s[i][y] = s*rn2s[y];
    }
    // pass2: mw2 into smem (Q rows L1-resident)
    for (int c = t; c < CCH; c += 288) {
        const float4* row = Q4 + c*9;
        float a = 0.f;
        #pragma unroll
        for (int y4 = 0; y4 < 9; y4++) {
            float4 v = row[y4];
            a += v.x*rn2s[y4*4] + v.y*rn2s[y4*4+1] + v.z*rn2s[y4*4+2] + v.w*rn2s[y4*4+3];
        }
        mw2s[c] = a*(1.f/36.f);
    }
    __syncthreads();
    if (t < WAY*MID) {  // path1 conv1
        int i = t/MID, m = t%MID;
        float a = b1[m];
        #pragma unroll
        for (int y = 0; y < HW; y++) a += w1[m*HW + y]*ch1s[i][y];
        int p = (b*WAY + i)*NQ + q;
        g_yv[p*MID + m] = a;
        atomicAdd(&g_stats[m], a); atomicAdd(&g_stats[MID + m], a*a);
    }
    // path2 conv1 via pw1: 30 outputs x 8-thread groups
    if (t >= 32 && t < 288) {
        int tt = t - 32;
        int g = tt >> 3, j = tt & 7;    // g < 32, use g < 30
        float a = 0.f;
        if (g < 30) {
            int i = g/MID, m = g%MID;
            const float4* pw = (const float4*)(g_pw1 + (size_t)((b*WAY + i)*MID + m)*CCH);
            const float4* m4 = (const float4*)mw2s;
            #pragma unroll
            for (int k = 0; k < 16; k++) {
                float4 u = pw[j + 8*k], w = m4[j + 8*k];
                a += u.x*w.x + u.y*w.y + u.z*w.z + u.w*w.w;
            }
        }
        a += __shfl_xor_sync(0xffffffffu, a, 4);
        a += __shfl_xor_sync(0xffffffffu, a, 2);
        a += __shfl_xor_sync(0xffffffffu, a, 1);
        if (j == 0 && g < 30) {
            int i = g/MID, m = g%MID;
            a += b1[m];
            int p = (b*WAY + i)*NQ + q;
            g_yv[PAIRS*MID + p*MID + m] = a;
            atomicAdd(&g_stats[12 + m], a); atomicAdd(&g_stats[18 + m], a*a);
        }
    }
}

// fused BN-finalize + conv2 (aw) + v2 matvec; per (bi, q-chunk25)
__global__ void __launch_bounds__(288) k_awv2(const float* __restrict__ gam,
                                              const float* __restrict__ bet,
                                              const float* __restrict__ w2,
                                              const float* __restrict__ b2) {
    int bi = blockIdx.x; int qc = blockIdx.y*25;
    int b = bi/WAY;
    int pb = bi*NQ + qc;
    const float* P = g_protos + (size_t)bi*CHW;
    __shared__ float bnps[24];
    __shared__ float hsh[25][12];
    __shared__ float wv2s[25*HW];
    __shared__ float tile[32*37];
    __shared__ float rn1s[HW];
    int t = threadIdx.x;
    if (t < 12) {
        int path = t/MID, m = t%MID;
        float sum = g_stats[path*12 + m];
        float sqs = g_stats[path*12 + MID + m];
        float mu  = sum/(float)PAIRS;
        float var = sqs/(float)PAIRS - mu*mu;
        bnps[path*12 + m]       = mu;
        bnps[path*12 + MID + m] = rsqrtf(var + 1e-5f);
    }
    if (t >= 64 && t < 64 + HW) rn1s[t - 64] = g_rn1[bi*HW + (t - 64)];
    __syncthreads();
    if (t < 300) {
        int pl = t/12, tt = t%12, path = tt/MID, m = tt%MID;
        int p = pb + pl;
        float v = g_yv[path*PAIRS*MID + p*MID + m];
        float z = gam[m]*(v - bnps[path*12 + m])*bnps[path*12 + MID + m] + bet[m];
        hsh[pl][tt] = fmaxf(z, 0.f);
    }
    __syncthreads();
    for (int idx = t; idx < 25*72; idx += 288) {
        int pl = idx/72, tt = idx%72, path = tt/HW, k = tt%HW;
        int p = pb + pl; int bq = b*NQ + qc + pl;
        float a = b2[k];
        #pragma unroll
        for (int m = 0; m < MID; m++) a += w2[k*MID + m]*hsh[pl][path*MID + m];
        if (path == 0) g_wv1[p*HW + k] = a * g_rn2[bq*HW + k];
        else           wv2s[pl*HW + k] = a * rn1s[k];
    }
    __syncthreads();
    // v2[p,c] = Σ_x P[c,x]·wv2[p,x]
    int x = t%36, trow = t/36;
    for (int c0 = 0; c0 < CCH; c0 += 32) {
        #pragma unroll
        for (int j = 0; j < 4; j++)
            tile[(trow + 8*j)*37 + x] = P[(c0 + trow + 8*j)*HW + x];
        __syncthreads();
        #pragma unroll
        for (int r = 0; r < 3; r++) {
            int item = t + 288*r;
            if (item < 800) {
                int q = item >> 5, c_l = item & 31;
                float a = 0.f;
                #pragma unroll
                for (int xx = 0; xx < HW; xx++) a += tile[c_l*37 + xx]*wv2s[q*HW + xx];
                g_v2[(size_t)(pb + q)*CCH + c0 + c_l] = a;
            }
        }
        __syncthreads();
    }
}

// fused v1 + s2 + attsel; per bq, smem-tiled Q pass
__global__ void __launch_bounds__(288) k_v1s2(const float* __restrict__ Q,
                                              const float* __restrict__ qt) {
    int bq = blockIdx.x; int b = bq/NQ, q = bq%NQ;
    int t = threadIdx.x;
    __shared__ float v2s[WAY*CCH];
    __shared__ float wv1s[WAY][HW];
    __shared__ float tile[32*37];
    __shared__ float rn2s[HW];
    __shared__ float s2s[WAY][HW];
    __shared__ float mx[WAY], sm[WAY], qts[WAY];
    {
        float4* dst = (float4*)v2s;
        for (int i4 = t; i4 < WAY*CCH/4; i4 += 288) {
            int i = i4/(CCH/4);
            const float4* src = (const float4*)(g_v2 + (size_t)((b*WAY + i)*NQ + q)*CCH);
            dst[i4] = src[i4 - i*(CCH/4)];
        }
    }
    if (t < WAY*HW) wv1s[t/HW][t%HW] = g_wv1[((b*WAY + t/HW)*NQ + q)*HW + t%HW];
    if (t < HW) rn2s[t] = g_rn2[bq*HW + t];
    if (t < WAY) qts[t] = qt[(size_t)bq*WAY + t];
    __syncthreads();
    const float* Qb = Q + (size_t)bq*CHW;
    int x = t%36, trow = t/36;
    int si = (t < 180) ? t/36 : 0;
    int sx = t%36;
    float s2a = 0.f;
    for (int c0 = 0; c0 < CCH; c0 += 32) {
        #pragma unroll
        for (int j = 0; j < 4; j++)
            tile[(trow + 8*j)*37 + x] = Qb[(c0 + trow + 8*j)*HW + x];
        __syncthreads();
        if (t < 160) {
            int i = t >> 5, c_l = t & 31;
            float a = 0.f;
            #pragma unroll
            for (int y = 0; y < HW; y++) a += tile[c_l*37 + y]*wv1s[i][y];
            g_v1[(size_t)((b*WAY + i)*NQ + q)*CCH + c0 + c_l] = a;
        }
        if (t < 180) {
            #pragma unroll
            for (int c = 0; c < 32; c++) s2a += v2s[si*CCH + c0 + c]*tile[c*37 + sx];
        }
        __syncthreads();
    }
    if (t < 180) s2s[si][sx] = s2a * rn2s[sx] * (1.f/36.f);
    __syncthreads();
    if (t < WAY) {
        float m = -1e30f;
        #pragma unroll
        for (int yy = 0; yy < HW; yy++) m = fmaxf(m, s2s[t][yy]);
        mx[t] = m;
    }
    __syncthreads();
    if (t < 180) s2s[si][sx] = expf((s2s[si][sx] - mx[si])*40.f);
    __syncthreads();
    if (t < WAY) {
        float s = 0.f;
        #pragma unroll
        for (int yy = 0; yy < HW; yy++) s += s2s[t][yy];
        sm[t] = s;
    }
    __syncthreads();
    if (t < HW) {
        float a = 0.f;
        #pragma unroll
        for (int i = 0; i < WAY; i++) a += (s2s[i][t]/sm[i] + 1.f)*qts[i];
        g_asel[bq*HW + t] = a;
    }
}

// fused s1 + softmax + proto-pool + l2norm; per (bi, q-chunk16)
__global__ void __launch_bounds__(288) k_s1pool() {
    int bi = blockIdx.x; int qc = blockIdx.y*16;
    const float* P = g_protos + (size_t)bi*CHW;
    __shared__ float v1s[16*CCH];
    __shared__ float tile[32*37];
    __shared__ float att[16][HW];
    __shared__ float rn1s[HW];
    __shared__ float mx[16], sm[16];
    __shared__ float pnfs[16];
    int t = threadIdx.x;
    if (t < HW) rn1s[t] = g_rn1[bi*HW + t];
    {
        float4* dst = (float4*)v1s;
        const float4* src = (const float4*)g_v1;
        for (int i4 = t; i4 < 16*CCH/4; i4 += 288) {
            int ql = i4 >> 7;
            int qq = qc + ql;
            dst[i4] = (qq < NQ) ? src[(size_t)(bi*NQ + qq)*(CCH/4) + (i4 & 127)]
                                : make_float4(0.f,0.f,0.f,0.f);
        }
    }
    __syncthreads();
    int x = t%36, trow = t/36;
    float acc0 = 0.f, acc1 = 0.f;
    for (int c0 = 0; c0 < CCH; c0 += 32) {
        #pragma unroll
        for (int j = 0; j < 4; j++)
            tile[(trow + 8*j)*37 + x] = P[(c0 + trow + 8*j)*HW + x];
        __syncthreads();
        #pragma unroll
        for (int c = 0; c < 32; c++) {
            float pv = tile[c*37 + x];
            acc0 += v1s[trow*CCH + c0 + c]*pv;
            acc1 += v1s[(trow+8)*CCH + c0 + c]*pv;
        }
        __syncthreads();
    }
    att[trow][x]   = acc0*rn1s[x]*(1.f/36.f);
    att[trow+8][x] = acc1*rn1s[x]*(1.f/36.f);
    __syncthreads();
    if (t < 16) {
        float m = -1e30f;
        #pragma unroll
        for (int xx = 0; xx < HW; xx++) m = fmaxf(m, att[t][xx]);
        mx[t] = m;
    }
    __syncthreads();
    att[trow][x]   = expf((att[trow][x]   - mx[trow])*40.f);
    att[trow+8][x] = expf((att[trow+8][x] - mx[trow+8])*40.f);
    __syncthreads();
    if (t < 16) {
        float s = 0.f;
        #pragma unroll
        for (int xx = 0; xx < HW; xx++) s += att[t][xx];
        sm[t] = s;
    }
    __syncthreads();
    att[trow][x]   = att[trow][x]/sm[trow]     + 1.f;
    att[trow+8][x] = att[trow+8][x]/sm[trow+8] + 1.f;
    __syncthreads();
    int q_a = t >> 5, c_l = t & 31;
    int q_b = q_a + 9;
    float ssq_a = 0.f, ssq_b = 0.f;
    for (int c0 = 0; c0 < CCH; c0 += 32) {
        #pragma unroll
        for (int j = 0; j < 4; j++)
            tile[(trow + 8*j)*37 + x] = P[(c0 + trow + 8*j)*HW + x];
        __syncthreads();
        {
            float a = 0.f;
            #pragma unroll
            for (int xx = 0; xx < HW; xx++) a += tile[c_l*37 + xx]*att[q_a][xx];
            a *= (1.f/36.f);
            v1s[q_a*CCH + c0 + c_l] = a;
            ssq_a += a*a;
        }
        if (q_b < 16) {
            float a = 0.f;
            #pragma unroll
            for (int xx = 0; xx < HW; xx++) a += tile[c_l*37 + xx]*att[q_b][xx];
            a *= (1.f/36.f);
            v1s[q_b*CCH + c0 + c_l] = a;
            ssq_b += a*a;
        }
        __syncthreads();
    }
    #pragma unroll
    for (int off = 16; off > 0; off >>= 1) {
        ssq_a += __shfl_xor_sync(0xffffffffu, ssq_a, off);
        ssq_b += __shfl_xor_sync(0xffffffffu, ssq_b, off);
    }
    int lane = t & 31, warp = t >> 5;
    if (lane == 0) {
        pnfs[warp] = 1.f/fmaxf(sqrtf(ssq_a), 1e-12f);
        if (warp < 7) pnfs[warp + 9] = 1.f/fmaxf(sqrtf(ssq_b), 1e-12f);
    }
    __syncthreads();
    for (int idx = t; idx < 16*CCH; idx += 288) {
        int ql = idx >> 9; int qq = qc + ql;
        if (qq < NQ) g_v1[(size_t)(bi*NQ + qq)*CCH + (idx & 511)] = v1s[idx]*pnfs[ql];
    }
}

// logits GEMM + fused cls_scores
__global__ void __launch_bounds__(128) k_logit(const float* __restrict__ Q,
                                               const float* __restrict__ cw,
                                               const float* __restrict__ cb,
                                               float* __restrict__ out1,
                                               float* __restrict__ out2) {
    int n0 = blockIdx.x*64;
    int t = threadIdx.x;
    int tn = t & 15, tm = t >> 4;
    __shared__ float shAB[2240];
    __shared__ float pools[3*WAY*CCH];
    int bq0 = n0/36;
    {
        float4* dst = (float4*)pools;
        const float4* src = (const float4*)g_v1;
        for (int i4 = t; i4 < 3*WAY*(CCH/4); i4 += 128) {
            int r = i4/640; int rem = i4 - r*640; int i = rem >> 7; int c4 = rem & 127;
            int bq = bq0 + r;
            float4 v = make_float4(0.f,0.f,0.f,0.f);
            if (bq < BB*NQ) {
                int b = bq/NQ, q = bq%NQ;
                v = src[(size_t)((b*WAY + i)*NQ + q)*(CCH/4) + c4];
            }
            dst[i4] = v;
        }
    }
    int nn_l = t & 63, kgrp = t >> 6;
    int nglob = n0 + nn_l;
    bool nval = nglob < NTOT;
    int bq_l = nval ? nglob/36 : 0;
    int x_l  = nval ? nglob%36 : 0;
    const float* qbase = Q + (size_t)bq_l*CHW + x_l;
    int o_a = t >> 1, ka = (t & 1)*8;
    float acc[8][4];
    float accc[4][WAY];
    #pragma unroll
    for (int r = 0; r < 8; r++)
        #pragma unroll
        for (int j = 0; j < 4; j++) acc[r][j] = 0.f;
    #pragma unroll
    for (int j = 0; j < 4; j++)
        #pragma unroll
        for (int i = 0; i < WAY; i++) accc[j][i] = 0.f;
    int rj[4];
    #pragma unroll
    for (int j = 0; j < 4; j++) {
        int n = n0 + tn*4 + j;
        rj[j] = (n < NTOT) ? (n/36 - bq0) : 0;
    }
    for (int k0 = 0; k0 < CCH; k0 += 16) {
        float4 av0 = *(const float4*)(cw + o_a*CCH + k0 + ka);
        float4 av1 = *(const float4*)(cw + o_a*CCH + k0 + ka + 4);
        shAB[(ka+0)*72 + o_a] = av0.x; shAB[(ka+1)*72 + o_a] = av0.y;
        shAB[(ka+2)*72 + o_a] = av0.z; shAB[(ka+3)*72 + o_a] = av0.w;
        shAB[(ka+4)*72 + o_a] = av1.x; shAB[(ka+5)*72 + o_a] = av1.y;
        shAB[(ka+6)*72 + o_a] = av1.z; shAB[(ka+7)*72 + o_a] = av1.w;
        #pragma unroll
        for (int j = 0; j < 8; j++) {
            int kk = kgrp*8 + j;
            shAB[1152 + kk*68 + nn_l] = nval ? qbase[(size_t)(k0 + kk)*HW] : 0.f;
        }
        __syncthreads();
        #pragma unroll
        for (int k = 0; k < 16; k++) {
            float4 af0 = *(const float4*)&shAB[k*72 + tm*8];
            float4 af1 = *(const float4*)&shAB[k*72 + tm*8 + 4];
            float4 bf  = *(const float4*)&shAB[1152 + k*68 + tn*4];
            float am[8] = {af0.x,af0.y,af0.z,af0.w,af1.x,af1.y,af1.z,af1.w};
            float bn[4] = {bf.x,bf.y,bf.z,bf.w};
            #pragma unroll
            for (int r = 0; r < 8; r++)
                #pragma unroll
                for (int j = 0; j < 4; j++) acc[r][j] += am[r]*bn[j];
        }
        #pragma unroll
        for (int kk2 = 0; kk2 < 2; kk2++) {
            int kk = tm*2 + kk2;
            #pragma unroll
            for (int j = 0; j < 4; j++) {
                float bn = shAB[1152 + kk*68 + tn*4 + j];
                #pragma unroll
                for (int i = 0; i < WAY; i++)
                    accc[j][i] += pools[rj[j]*WAY*CCH + i*CCH + k0 + kk]*bn;
            }
        }
        __syncthreads();
    }
    #pragma unroll
    for (int j = 0; j < 4; j++) {
        int n = n0 + tn*4 + j;
        if (n >= NTOT) continue;
        int bq = n/36, x = n%36;
        float av = g_asel[n];
        #pragma unroll
        for (int r = 0; r < 8; r++) {
            int o = tm*8 + r;
            out1[((size_t)bq*NCLS + o)*HW + x] = acc[r][j]*av + cb[o];
        }
    }
    #pragma unroll
    for (int j = 0; j < 4; j++)
        #pragma unroll
        for (int i = 0; i < WAY; i++)
            accc[j][i] += __shfl_xor_sync(0xffffffffu, accc[j][i], 16);
    if ((tm & 1) == 0) {
        int g = tm >> 1;
        #pragma unroll
        for (int j = 0; j < 4; j++)
            #pragma unroll
            for (int i = 0; i < WAY; i++)
                shAB[g*320 + (tn*4 + j)*WAY + i] = accc[j][i];
    }
    __syncthreads();
    for (int idx = t; idx < 320; idx += 128) {
        int n_l = idx/WAY, i = idx%WAY;
        int n = n0 + n_l;
        if (n < NTOT) {
            float s = shAB[idx] + shAB[320 + idx] + shAB[640 + idx] + shAB[960 + idx];
            int bq = n/36, x = n%36;
            out2[((size_t)bq*WAY + i)*HW + x] = 7.f * g_rn2[n] * s;
        }
    }
}

// ---------------- launch ----------------
extern "C" void kernel_launch(void* const* d_in, const int* in_sizes, int n_in,
                              void* d_out, int out_size) {
    (void)in_sizes; (void)n_in; (void)out_size;
    const float* support = (const float*)d_in[0];
    const float* query   = (const float*)d_in[1];
    const float* st      = (const float*)d_in[2];
    const float* qt      = (const float*)d_in[3];
    const float* w1      = (const float*)d_in[4];
    const float* b1      = (const float*)d_in[5];
    const float* gam     = (const float*)d_in[6];
    const float* bet     = (const float*)d_in[7];
    const float* w2      = (const float*)d_in[8];
    const float* b2      = (const float*)d_in[9];
    const float* cw      = (const float*)d_in[10];
    const float* cb      = (const float*)d_in[11];
    float* out1 = (float*)d_out;                               // logits 600*64*36
    float* out2 = out1 + (size_t)BB*NQ*NCLS*HW;                // cls_scores 600*5*36

    k_protos   <<<dim3(16, BB), 288>>>(support, st);
    k_prep1    <<<BB*WAY, 288>>>(w1);
    k_prep2ch1 <<<BB*NQ, 288>>>(query, w1, b1);
    k_awv2     <<<dim3(BB*WAY, 3), 288>>>(gam, bet, w2, b2);
    k_v1s2     <<<BB*NQ, 288>>>(query, qt);
    k_s1pool   <<<dim3(BB*WAY, 5), 288>>>();
    k_logit    <<<(NTOT + 63)/64, 128>>>(query, cw, cb, out1, out2);
}

// round 6
// speedup vs baseline: 2.3774x; 1.0157x over previous
#include <cuda_runtime.h>
#include <math.h>

#define BB   8
#define NS   25
#define NQ   75
#define WAY  5
#define CCH  512
#define HW   36
#define MID  6
#define NCLS 64
#define PAIRS (BB*WAY*NQ)   /* 3000 */
#define CHW  (CCH*HW)       /* 18432 */
#define CHW4 (CHW/4)        /* 4608 */
#define NTOT (BB*NQ*HW)     /* 21600 */

// ---------------- scratch ----------------
__device__ float g_protos[BB*WAY*CHW];     // [b,i,c,x]
__device__ float g_rn1 [BB*WAY*HW];
__device__ float g_mw1 [BB*WAY*CCH];
__device__ float g_rn2 [BB*NQ*HW];
__device__ float g_mw2 [BB*NQ*CCH];
__device__ float g_yv  [2*PAIRS*MID];
__device__ float g_stats[24];
__device__ float g_wv1 [PAIRS*HW];
__device__ float g_v1  [PAIRS*CCH];        // v1, later NORMALIZED pooled
__device__ float g_v2  [PAIRS*CCH];
__device__ float g_asel[BB*NQ*HW];

// prototypes (float4) + zero stats
__global__ void __launch_bounds__(288) k_protos(const float* __restrict__ sup,
                                                const float* __restrict__ st) {
    int b = blockIdx.y, t = threadIdx.x;
    if (blockIdx.x == 0 && b == 0 && t < 24) g_stats[t] = 0.f;
    __shared__ float sts[NS*WAY];
    __shared__ float rcnt[WAY];
    if (t < NS*WAY) sts[t] = st[b*NS*WAY + t];
    __syncthreads();
    if (t < WAY) { float s = 0.f; for (int n = 0; n < NS; n++) s += sts[n*WAY + t]; rcnt[t] = 1.f/s; }
    __syncthreads();
    int d4 = blockIdx.x*288 + t;
    const float4* sb = (const float4*)sup + (size_t)b*NS*CHW4 + d4;
    float4 acc[WAY];
    #pragma unroll
    for (int w = 0; w < WAY; w++) acc[w] = make_float4(0.f,0.f,0.f,0.f);
    for (int n = 0; n < NS; n++) {
        float4 v = sb[(size_t)n*CHW4];
        #pragma unroll
        for (int w = 0; w < WAY; w++) {
            float s = sts[n*WAY + w];
            acc[w].x += s*v.x; acc[w].y += s*v.y; acc[w].z += s*v.z; acc[w].w += s*v.w;
        }
    }
    #pragma unroll
    for (int w = 0; w < WAY; w++) {
        float r = rcnt[w];
        float4 o = make_float4(acc[w].x*r, acc[w].y*r, acc[w].z*r, acc[w].w*r);
        ((float4*)g_protos)[(size_t)(b*WAY + w)*CHW4 + d4] = o;
    }
}

// per (b,i): rn1, mw1
__global__ void __launch_bounds__(288) k_prep1() {
    int bi = blockIdx.x, t = threadIdx.x;
    const float4* P4 = (const float4*)(g_protos + (size_t)bi*CHW);
    __shared__ float part[288*4];
    __shared__ float rn1s[HW];
    float s0=0.f,s1=0.f,s2=0.f,s3=0.f;
    #pragma unroll 4
    for (int k = 0; k < 16; k++) {
        float4 v = P4[t + 288*k];
        s0 += v.x*v.x; s1 += v.y*v.y; s2 += v.z*v.z; s3 += v.w*v.w;
    }
    part[4*t]=s0; part[4*t+1]=s1; part[4*t+2]=s2; part[4*t+3]=s3;
    __syncthreads();
    if (t < HW) {
        int y4 = t >> 2, j = t & 3;
        float s = 0.f;
        #pragma unroll
        for (int m = 0; m < 32; m++) s += part[4*(y4 + 9*m) + j];
        float r = 1.f/fmaxf(sqrtf(s), 1e-12f);
        rn1s[t] = r; g_rn1[bi*HW + t] = r;
    }
    __syncthreads();
    for (int c = t; c < CCH; c += 288) {
        const float4* row = P4 + c*9;
        float a = 0.f;
        #pragma unroll
        for (int y4 = 0; y4 < 9; y4++) {
            float4 v = row[y4];
            a += v.x*rn1s[y4*4] + v.y*rn1s[y4*4+1] + v.z*rn1s[y4*4+2] + v.w*rn1s[y4*4+3];
        }
        g_mw1[bi*CCH + c] = a*(1.f/36.f);
    }
}

// fused prep2 + ch1(path1 conv1); per bq; writes rn2, mw2
__global__ void __launch_bounds__(288) k_prep2ch1(const float* __restrict__ Q,
                                                  const float* __restrict__ w1,
                                                  const float* __restrict__ b1) {
    int bq = blockIdx.x; int b = bq/NQ, q = bq%NQ;
    int t = threadIdx.x;
    __shared__ float mw1s[WAY*CCH];
    __shared__ float redA[20][288];
    __shared__ float part[288*4];
    __shared__ float rn2s[HW];
    __shared__ float ch1s[WAY][HW];
    {
        const float4* src = (const float4*)(g_mw1 + b*WAY*CCH);
        float4* dst = (float4*)mw1s;
        for (int i4 = t; i4 < WAY*CCH/4; i4 += 288) dst[i4] = src[i4];
    }
    __syncthreads();
    const float4* Q4 = (const float4*)(Q + (size_t)bq*CHW);
    float aacc[WAY][4];
    float sq[4] = {0.f,0.f,0.f,0.f};
    #pragma unroll
    for (int i = 0; i < WAY; i++)
        #pragma unroll
        for (int j = 0; j < 4; j++) aacc[i][j] = 0.f;
    #pragma unroll 4
    for (int k = 0; k < 16; k++) {
        int idx = t + 288*k;
        int c = idx/9;
        float4 v = Q4[idx];
        sq[0] += v.x*v.x; sq[1] += v.y*v.y; sq[2] += v.z*v.z; sq[3] += v.w*v.w;
        #pragma unroll
        for (int i = 0; i < WAY; i++) {
            float w = mw1s[i*CCH + c];
            aacc[i][0] += w*v.x; aacc[i][1] += w*v.y; aacc[i][2] += w*v.z; aacc[i][3] += w*v.w;
        }
    }
    #pragma unroll
    for (int j = 0; j < 4; j++) part[4*t + j] = sq[j];
    #pragma unroll
    for (int i = 0; i < WAY; i++)
        #pragma unroll
        for (int j = 0; j < 4; j++) redA[i*4 + j][t] = aacc[i][j];
    __syncthreads();
    if (t < HW) {
        int y4 = t >> 2, j = t & 3;
        float s = 0.f;
        #pragma unroll
        for (int m = 0; m < 32; m++) s += part[4*(y4 + 9*m) + j];
        float r = 1.f/fmaxf(sqrtf(s), 1e-12f);
        rn2s[t] = r; g_rn2[bq*HW + t] = r;
    }
    __syncthreads();
    if (t < WAY*HW) {
        int i = t/HW, y = t%HW;
        int y4 = y >> 2, j = y & 3;
        float s = 0.f;
        #pragma unroll
        for (int m = 0; m < 32; m++) s += redA[i*4 + j][y4 + 9*m];
        ch1s[i][y] = s*rn2s[y];
    }
    // pass2: mw2 (Q rows L1-resident)
    for (int c = t; c < CCH; c += 288) {
        const float4* row = Q4 + c*9;
        float a = 0.f;
        #pragma unroll
        for (int y4 = 0; y4 < 9; y4++) {
            float4 v = row[y4];
            a += v.x*rn2s[y4*4] + v.y*rn2s[y4*4+1] + v.z*rn2s[y4*4+2] + v.w*rn2s[y4*4+3];
        }
        g_mw2[bq*CCH + c] = a*(1.f/36.f);
    }
    __syncthreads();
    if (t < WAY*MID) {  // path1 conv1
        int i = t/MID, m = t%MID;
        float a = b1[m];
        #pragma unroll
        for (int y = 0; y < HW; y++) a += w1[m*HW + y]*ch1s[i][y];
        int p = (b*WAY + i)*NQ + q;
        g_yv[p*MID + m] = a;
        atomicAdd(&g_stats[m], a); atomicAdd(&g_stats[MID + m], a*a);
    }
}

// path2 conv input + conv1 + BN stats; per (bi, q-chunk16); smem-tiled P (c-chunk 64)
// EXACT round-4 math order: ch2[q,x] = rn1[x]*sum_c mw2[q,c]*P[c,x]; yv2 = b1 + sum_x w1*ch2
__global__ void __launch_bounds__(288) k_ch2f(const float* __restrict__ w1,
                                              const float* __restrict__ b1) {
    int bi = blockIdx.x; int qc = blockIdx.y*16;
    int b = bi/WAY;
    const float* P = g_protos + (size_t)bi*CHW;
    __shared__ float mw2s[16*CCH];   // 32KB
    __shared__ float tile[64*37];    // 9.47KB
    __shared__ float ch2s[16][HW];
    __shared__ float rn1s[HW];
    int t = threadIdx.x;
    if (t < HW) rn1s[t] = g_rn1[bi*HW + t];
    {
        float4* dst = (float4*)mw2s;
        const float4* src = (const float4*)g_mw2;
        for (int i4 = t; i4 < 16*128; i4 += 288) {
            int ql = i4 >> 7; int qq = qc + ql;
            dst[i4] = (qq < NQ) ? src[(size_t)(b*NQ + qq)*128 + (i4 & 127)]
                                : make_float4(0.f,0.f,0.f,0.f);
        }
    }
    __syncthreads();
    int q0 = t/36, x0 = t%36;          // thread owns (q0,x0) and (q0+8,x0); 576 = 2*288
    int q1 = q0 + 8;
    float acc0 = 0.f, acc1 = 0.f;
    for (int c0 = 0; c0 < CCH; c0 += 64) {
        for (int idx = t; idx < 64*36; idx += 288) {
            int r = idx/36, xx = idx%36;
            tile[r*37 + xx] = P[(c0 + r)*HW + xx];
        }
        __syncthreads();
        #pragma unroll 8
        for (int c = 0; c < 64; c++) {
            float pv = tile[c*37 + x0];
            acc0 += mw2s[q0*CCH + c0 + c]*pv;
            acc1 += mw2s[q1*CCH + c0 + c]*pv;
        }
        __syncthreads();
    }
    ch2s[q0][x0] = acc0*rn1s[x0];
    ch2s[q1][x0] = acc1*rn1s[x0];
    __syncthreads();
    if (t < 16*MID) {
        int g2 = t/MID, m = t%MID; int q2 = qc + g2;
        if (q2 < NQ) {
            float s = b1[m];
            #pragma unroll
            for (int xx = 0; xx < HW; xx++) s += w1[m*HW + xx]*ch2s[g2][xx];
            int p = bi*NQ + q2;
            g_yv[PAIRS*MID + p*MID + m] = s;
            atomicAdd(&g_stats[12 + m], s); atomicAdd(&g_stats[18 + m], s*s);
        }
    }
}

// fused BN-finalize + conv2 (aw) + v2 matvec; per (bi, q-chunk25); c-chunk 64
__global__ void __launch_bounds__(288) k_awv2(const float* __restrict__ gam,
                                              const float* __restrict__ bet,
                                              const float* __restrict__ w2,
                                              const float* __restrict__ b2) {
    int bi = blockIdx.x; int qc = blockIdx.y*25;
    int b = bi/WAY;
    int pb = bi*NQ + qc;
    const float* P = g_protos + (size_t)bi*CHW;
    __shared__ float bnps[24];
    __shared__ float hsh[25][12];
    __shared__ float wv2s[25*HW];
    __shared__ float tile[64*37];
    __shared__ float rn1s[HW];
    int t = threadIdx.x;
    if (t < 12) {
        int path = t/MID, m = t%MID;
        float sum = g_stats[path*12 + m];
        float sqs = g_stats[path*12 + MID + m];
        float mu  = sum/(float)PAIRS;
        float var = sqs/(float)PAIRS - mu*mu;
        bnps[path*12 + m]       = mu;
        bnps[path*12 + MID + m] = rsqrtf(var + 1e-5f);
    }
    if (t >= 64 && t < 64 + HW) rn1s[t - 64] = g_rn1[bi*HW + (t - 64)];
    __syncthreads();
    for (int idx = t; idx < 300; idx += 288) {   // FIXED: cover all 25 pairs
        int pl = idx/12, tt = idx%12, path = tt/MID, m = tt%MID;
        int p = pb + pl;
        float v = g_yv[path*PAIRS*MID + p*MID + m];
        float z = gam[m]*(v - bnps[path*12 + m])*bnps[path*12 + MID + m] + bet[m];
        hsh[pl][tt] = fmaxf(z, 0.f);
    }
    __syncthreads();
    for (int idx = t; idx < 25*72; idx += 288) {
        int pl = idx/72, tt = idx%72, path = tt/HW, k = tt%HW;
        int p = pb + pl; int bq = b*NQ + qc + pl;
        float a = b2[k];
        #pragma unroll
        for (int m = 0; m < MID; m++) a += w2[k*MID + m]*hsh[pl][path*MID + m];
        if (path == 0) g_wv1[p*HW + k] = a * g_rn2[bq*HW + k];
        else           wv2s[pl*HW + k] = a * rn1s[k];
    }
    __syncthreads();
    // v2[p,c] = sum_x P[c,x]*wv2[p,x]
    for (int c0 = 0; c0 < CCH; c0 += 64) {
        for (int idx = t; idx < 64*36; idx += 288) {
            int r = idx/36, xx = idx%36;
            tile[r*37 + xx] = P[(c0 + r)*HW + xx];
        }
        __syncthreads();
        #pragma unroll
        for (int r = 0; r < 6; r++) {
            int item = t + 288*r;
            if (item < 1600) {
                int q = item >> 6, c_l = item & 63;
                float a = 0.f;
                #pragma unroll
                for (int xx = 0; xx < HW; xx++) a += tile[c_l*37 + xx]*wv2s[q*HW + xx];
                g_v2[(size_t)(pb + q)*CCH + c0 + c_l] = a;
            }
        }
        __syncthreads();
    }
}

// fused v1 + s2 + attsel; per bq, smem-tiled Q pass (c-chunk 64)
__global__ void __launch_bounds__(288) k_v1s2(const float* __restrict__ Q,
                                              const float* __restrict__ qt) {
    int bq = blockIdx.x; int b = bq/NQ, q = bq%NQ;
    int t = threadIdx.x;
    __shared__ float v2s[WAY*CCH];
    __shared__ float wv1s[WAY][HW];
    __shared__ float tile[64*37];
    __shared__ float rn2s[HW];
    __shared__ float s2s[WAY][HW];
    __shared__ float mx[WAY], sm[WAY], qts[WAY];
    {
        float4* dst = (float4*)v2s;
        for (int i4 = t; i4 < WAY*CCH/4; i4 += 288) {
            int i = i4/(CCH/4);
            const float4* src = (const float4*)(g_v2 + (size_t)((b*WAY + i)*NQ + q)*CCH);
            dst[i4] = src[i4 - i*(CCH/4)];
        }
    }
    if (t < WAY*HW) wv1s[t/HW][t%HW] = g_wv1[((b*WAY + t/HW)*NQ + q)*HW + t%HW];
    if (t < HW) rn2s[t] = g_rn2[bq*HW + t];
    if (t < WAY) qts[t] = qt[(size_t)bq*WAY + t];
    __syncthreads();
    const float* Qb = Q + (size_t)bq*CHW;
    int si = (t < 180) ? t/36 : 0;
    int sx = t%36;
    float s2a = 0.f;
    for (int c0 = 0; c0 < CCH; c0 += 64) {
        for (int idx = t; idx < 64*36; idx += 288) {
            int r = idx/36, xx = idx%36;
            tile[r*37 + xx] = Qb[(c0 + r)*HW + xx];
        }
        __syncthreads();
        #pragma unroll
        for (int r = 0; r < 2; r++) {
            int item = t + 288*r;
            if (item < 320) {
                int i = item >> 6, c_l = item & 63;
                float a = 0.f;
                #pragma unroll
                for (int y = 0; y < HW; y++) a += tile[c_l*37 + y]*wv1s[i][y];
                g_v1[(size_t)((b*WAY + i)*NQ + q)*CCH + c0 + c_l] = a;
            }
        }
        if (t < 180) {
            #pragma unroll 8
            for (int c = 0; c < 64; c++) s2a += v2s[si*CCH + c0 + c]*tile[c*37 + sx];
        }
        __syncthreads();
    }
    if (t < 180) s2s[si][sx] = s2a * rn2s[sx] * (1.f/36.f);
    __syncthreads();
    if (t < WAY) {
        float m = -1e30f;
        #pragma unroll
        for (int yy = 0; yy < HW; yy++) m = fmaxf(m, s2s[t][yy]);
        mx[t] = m;
    }
    __syncthreads();
    if (t < 180) s2s[si][sx] = expf((s2s[si][sx] - mx[si])*40.f);
    __syncthreads();
    if (t < WAY) {
        float s = 0.f;
        #pragma unroll
        for (int yy = 0; yy < HW; yy++) s += s2s[t][yy];
        sm[t] = s;
    }
    __syncthreads();
    if (t < HW) {
        float a = 0.f;
        #pragma unroll
        for (int i = 0; i < WAY; i++) a += (s2s[i][t]/sm[i] + 1.f)*qts[i];
        g_asel[bq*HW + t] = a;
    }
}

// fused s1 + softmax + proto-pool + l2norm; per (bi, q-chunk16)
__global__ void __launch_bounds__(288) k_s1pool() {
    int bi = blockIdx.x; int qc = blockIdx.y*16;
    const float* P = g_protos + (size_t)bi*CHW;
    __shared__ float v1s[16*CCH];
    __shared__ float tile[64*37];
    __shared__ float att[16][HW];
    __shared__ float rn1s[HW];
    __shared__ float mx[16], sm[16];
    __shared__ float pnfs[16];
    int t = threadIdx.x;
    if (t < HW) rn1s[t] = g_rn1[bi*HW + t];
    {
        float4* dst = (float4*)v1s;
        const float4* src = (const float4*)g_v1;
        for (int i4 = t; i4 < 16*CCH/4; i4 += 288) {
            int ql = i4 >> 7;
            int qq = qc + ql;
            dst[i4] = (qq < NQ) ? src[(size_t)(bi*NQ + qq)*(CCH/4) + (i4 & 127)]
                                : make_float4(0.f,0.f,0.f,0.f);
        }
    }
    __syncthreads();
    int x = t%36, trow = t/36;
    float acc0 = 0.f, acc1 = 0.f;
    for (int c0 = 0; c0 < CCH; c0 += 64) {
        for (int idx = t; idx < 64*36; idx += 288) {
            int r = idx/36, xx = idx%36;
            tile[r*37 + xx] = P[(c0 + r)*HW + xx];
        }
        __syncthreads();
        #pragma unroll 8
        for (int c = 0; c < 64; c++) {
            float pv = tile[c*37 + x];
            acc0 += v1s[trow*CCH + c0 + c]*pv;
            acc1 += v1s[(trow+8)*CCH + c0 + c]*pv;
        }
        __syncthreads();
    }
    att[trow][x]   = acc0*rn1s[x]*(1.f/36.f);
    att[trow+8][x] = acc1*rn1s[x]*(1.f/36.f);
    __syncthreads();
    if (t < 16) {
        float m = -1e30f;
        #pragma unroll
        for (int xx = 0; xx < HW; xx++) m = fmaxf(m, att[t][xx]);
        mx[t] = m;
    }
    __syncthreads();
    att[trow][x]   = expf((att[trow][x]   - mx[trow])*40.f);
    att[trow+8][x] = expf((att[trow+8][x] - mx[trow+8])*40.f);
    __syncthreads();
    if (t < 16) {
        float s = 0.f;
        #pragma unroll
        for (int xx = 0; xx < HW; xx++) s += att[t][xx];
        sm[t] = s;
    }
    __syncthreads();
    att[trow][x]   = att[trow][x]/sm[trow]     + 1.f;
    att[trow+8][x] = att[trow+8][x]/sm[trow+8] + 1.f;
    __syncthreads();
    // pool phase (c-chunk 32, uses first 32 rows of tile)
    int q_a = t >> 5, c_l = t & 31;
    int q_b = q_a + 9;
    float ssq_a = 0.f, ssq_b = 0.f;
    for (int c0 = 0; c0 < CCH; c0 += 32) {
        #pragma unroll
        for (int j = 0; j < 4; j++)
            tile[(trow + 8*j)*37 + x] = P[(c0 + trow + 8*j)*HW + x];
        __syncthreads();
        {
            float a = 0.f;
            #pragma unroll
            for (int xx = 0; xx < HW; xx++) a += tile[c_l*37 + xx]*att[q_a][xx];
            a *= (1.f/36.f);
            v1s[q_a*CCH + c0 + c_l] = a;
            ssq_a += a*a;
        }
        if (q_b < 16) {
            float a = 0.f;
            #pragma unroll
            for (int xx = 0; xx < HW; xx++) a += tile[c_l*37 + xx]*att[q_b][xx];
            a *= (1.f/36.f);
            v1s[q_b*CCH + c0 + c_l] = a;
            ssq_b += a*a;
        }
        __syncthreads();
    }
    #pragma unroll
    for (int off = 16; off > 0; off >>= 1) {
        ssq_a += __shfl_xor_sync(0xffffffffu, ssq_a, off);
        ssq_b += __shfl_xor_sync(0xffffffffu, ssq_b, off);
    }
    int lane = t & 31, warp = t >> 5;
    if (lane == 0) {
        pnfs[warp] = 1.f/fmaxf(sqrtf(ssq_a), 1e-12f);
        if (warp < 7) pnfs[warp + 9] = 1.f/fmaxf(sqrtf(ssq_b), 1e-12f);
    }
    __syncthreads();
    for (int idx = t; idx < 16*CCH; idx += 288) {
        int ql = idx >> 9; int qq = qc + ql;
        if (qq < NQ) g_v1[(size_t)(bi*NQ + qq)*CCH + (idx & 511)] = v1s[idx]*pnfs[ql];
    }
}

// logits GEMM + fused cls_scores
__global__ void __launch_bounds__(128) k_logit(const float* __restrict__ Q,
                                               const float* __restrict__ cw,
                                               const float* __restrict__ cb,
                                               float* __restrict__ out1,
                                               float* __restrict__ out2) {
    int n0 = blockIdx.x*64;
    int t = threadIdx.x;
    int tn = t & 15, tm = t >> 4;
    __shared__ float shAB[2240];
    __shared__ float pools[3*WAY*CCH];
    int bq0 = n0/36;
    {
        float4* dst = (float4*)pools;
        const float4* src = (const float4*)g_v1;
        for (int i4 = t; i4 < 3*WAY*(CCH/4); i4 += 128) {
            int r = i4/640; int rem = i4 - r*640; int i = rem >> 7; int c4 = rem & 127;
            int bq = bq0 + r;
            float4 v = make_float4(0.f,0.f,0.f,0.f);
            if (bq < BB*NQ) {
                int b = bq/NQ, q = bq%NQ;
                v = src[(size_t)((b*WAY + i)*NQ + q)*(CCH/4) + c4];
            }
            dst[i4] = v;
        }
    }
    int nn_l = t & 63, kgrp = t >> 6;
    int nglob = n0 + nn_l;
    bool nval = nglob < NTOT;
    int bq_l = nval ? nglob/36 : 0;
    int x_l  = nval ? nglob%36 : 0;
    const float* qbase = Q + (size_t)bq_l*CHW + x_l;
    int o_a = t >> 1, ka = (t & 1)*8;
    float acc[8][4];
    float accc[4][WAY];
    #pragma unroll
    for (int r = 0; r < 8; r++)
        #pragma unroll
        for (int j = 0; j < 4; j++) acc[r][j] = 0.f;
    #pragma unroll
    for (int j = 0; j < 4; j++)
        #pragma unroll
        for (int i = 0; i < WAY; i++) accc[j][i] = 0.f;
    int rj[4];
    #pragma unroll
    for (int j = 0; j < 4; j++) {
        int n = n0 + tn*4 + j;
        rj[j] = (n < NTOT) ? (n/36 - bq0) : 0;
    }
    for (int k0 = 0; k0 < CCH; k0 += 16) {
        float4 av0 = *(const float4*)(cw + o_a*CCH + k0 + ka);
        float4 av1 = *(const float4*)(cw + o_a*CCH + k0 + ka + 4);
        shAB[(ka+0)*72 + o_a] = av0.x; shAB[(ka+1)*72 + o_a] = av0.y;
        shAB[(ka+2)*72 + o_a] = av0.z; shAB[(ka+3)*72 + o_a] = av0.w;
        shAB[(ka+4)*72 + o_a] = av1.x; shAB[(ka+5)*72 + o_a] = av1.y;
        shAB[(ka+6)*72 + o_a] = av1.z; shAB[(ka+7)*72 + o_a] = av1.w;
        #pragma unroll
        for (int j = 0; j < 8; j++) {
            int kk = kgrp*8 + j;
            shAB[1152 + kk*68 + nn_l] = nval ? qbase[(size_t)(k0 + kk)*HW] : 0.f;
        }
        __syncthreads();
        #pragma unroll
        for (int k = 0; k < 16; k++) {
            float4 af0 = *(const float4*)&shAB[k*72 + tm*8];
            float4 af1 = *(const float4*)&shAB[k*72 + tm*8 + 4];
            float4 bf  = *(const float4*)&shAB[1152 + k*68 + tn*4];
            float am[8] = {af0.x,af0.y,af0.z,af0.w,af1.x,af1.y,af1.z,af1.w};
            float bn[4] = {bf.x,bf.y,bf.z,bf.w};
            #pragma unroll
            for (int r = 0; r < 8; r++)
                #pragma unroll
                for (int j = 0; j < 4; j++) acc[r][j] += am[r]*bn[j];
        }
        #pragma unroll
        for (int kk2 = 0; kk2 < 2; kk2++) {
            int kk = tm*2 + kk2;
            #pragma unroll
            for (int j = 0; j < 4; j++) {
                float bn = shAB[1152 + kk*68 + tn*4 + j];
                #pragma unroll
                for (int i = 0; i < WAY; i++)
                    accc[j][i] += pools[rj[j]*WAY*CCH + i*CCH + k0 + kk]*bn;
            }
        }
        __syncthreads();
    }
    #pragma unroll
    for (int j = 0; j < 4; j++) {
        int n = n0 + tn*4 + j;
        if (n >= NTOT) continue;
        int bq = n/36, x = n%36;
        float av = g_asel[n];
        #pragma unroll
        for (int r = 0; r < 8; r++) {
            int o = tm*8 + r;
            out1[((size_t)bq*NCLS + o)*HW + x] = acc[r][j]*av + cb[o];
        }
    }
    #pragma unroll
    for (int j = 0; j < 4; j++)
        #pragma unroll
        for (int i = 0; i < WAY; i++)
            accc[j][i] += __shfl_xor_sync(0xffffffffu, accc[j][i], 16);
    if ((tm & 1) == 0) {
        int g = tm >> 1;
        #pragma unroll
        for (int j = 0; j < 4; j++)
            #pragma unroll
            for (int i = 0; i < WAY; i++)
                shAB[g*320 + (tn*4 + j)*WAY + i] = accc[j][i];
    }
    __syncthreads();
    for (int idx = t; idx < 320; idx += 128) {
        int n_l = idx/WAY, i = idx%WAY;
        int n = n0 + n_l;
        if (n < NTOT) {
            float s = shAB[idx] + shAB[320 + idx] + shAB[640 + idx] + shAB[960 + idx];
            int bq = n/36, x = n%36;
            out2[((size_t)bq*WAY + i)*HW + x] = 7.f * g_rn2[n] * s;
        }
    }
}

// ---------------- launch ----------------
extern "C" void kernel_launch(void* const* d_in, const int* in_sizes, int n_in,
                              void* d_out, int out_size) {
    (void)in_sizes; (void)n_in; (void)out_size;
    const float* support = (const float*)d_in[0];
    const float* query   = (const float*)d_in[1];
    const float* st      = (const float*)d_in[2];
    const float* qt      = (const float*)d_in[3];
    const float* w1      = (const float*)d_in[4];
    const float* b1      = (const float*)d_in[5];
    const float* gam     = (const float*)d_in[6];
    const float* bet     = (const float*)d_in[7];
    const float* w2      = (const float*)d_in[8];
    const float* b2      = (const float*)d_in[9];
    const float* cw      = (const float*)d_in[10];
    const float* cb      = (const float*)d_in[11];
    float* out1 = (float*)d_out;                               // logits 600*64*36
    float* out2 = out1 + (size_t)BB*NQ*NCLS*HW;                // cls_scores 600*5*36

    k_protos   <<<dim3(16, BB), 288>>>(support, st);
    k_prep1    <<<BB*WAY, 288>>>();
    k_prep2ch1 <<<BB*NQ, 288>>>(query, w1, b1);
    k_ch2f     <<<dim3(BB*WAY, 5), 288>>>(w1, b1);
    k_awv2     <<<dim3(BB*WAY, 3), 288>>>(gam, bet, w2, b2);
    k_v1s2     <<<BB*NQ, 288>>>(query, qt);
    k_s1pool   <<<dim3(BB*WAY, 5), 288>>>();
    k_logit    <<<(NTOT + 63)/64, 128>>>(query, cw, cb, out1, out2);
}